// round 12
// baseline (speedup 1.0000x reference)
#include <cuda_runtime.h>
#include <cuda_fp16.h>
#include <math.h>
#include <stdint.h>

#define Cc   256
#define Hh   128
#define Wwid 128
#define HW   16384
#define CHW  4194304
#define Bb   8

// ---------------- static scratch ----------------
__device__ __align__(1024) __half g_bufAh[(size_t)Bb * CHW];   // conv1/conv4 out (fp16)
__device__ __align__(1024) __half g_bufBh[(size_t)Bb * CHW];   // dw3x3 out (fp16)
__device__ __align__(1024) __half g_bufX1h[(size_t)Bb * CHW];  // x1 residual (fp16)
__device__ __align__(1024) __half g_XcA[(size_t)Bb * HW * 256]; // B operand fp16
__device__ __align__(1024) __half g_XcB[(size_t)Bb * HW * 256];
__device__ __align__(1024) __half g_Abuf[(size_t)Bb * 256 * 256]; // A fp16
__device__ float  g_bias2[Bb * Cc];
__device__ double g_part[Bb * 256 * 2];      // GN1 partials (from prep1)
__device__ double g_part2[Bb * 256 * 2];     // GN2 partials (from gemm3 epilogue)
__device__ float  g_ppart[(size_t)Bb * Cc * 256];
__device__ float  g_att[Bb * Cc];

__device__ __forceinline__ float gelu1(float x) {
    return 0.5f * x * (1.0f + erff(x * 0.70710678118654752440f));
}

// ---------------- PTX helpers ----------------
__device__ __forceinline__ uint32_t smem_u32(const void* p) {
    uint32_t a;
    asm("{ .reg .u64 t; cvta.to.shared.u64 t, %1; cvt.u32.u64 %0, t; }" : "=r"(a) : "l"(p));
    return a;
}
#define SWZ128(off) ((off) ^ (((off) >> 3) & 0x70))
#define CP_ASYNC16(sa, g) asm volatile("cp.async.cg.shared.global [%0], [%1], 16;" :: "r"(sa), "l"(g) : "memory")
#define CP_COMMIT() asm volatile("cp.async.commit_group;" ::: "memory")
#define CP_WAIT1()  asm volatile("cp.async.wait_group 1;" ::: "memory")
#define CP_WAIT0()  asm volatile("cp.async.wait_group 0;" ::: "memory")

__device__ __forceinline__ void ldsm4(uint32_t& r0, uint32_t& r1, uint32_t& r2, uint32_t& r3,
                                      uint32_t a) {
    asm volatile("ldmatrix.sync.aligned.m8n8.x4.shared.b16 {%0,%1,%2,%3}, [%4];"
                 : "=r"(r0), "=r"(r1), "=r"(r2), "=r"(r3) : "r"(a));
}
__device__ __forceinline__ void mma16816(float* c, uint32_t a0, uint32_t a1, uint32_t a2,
                                         uint32_t a3, uint32_t b0, uint32_t b1) {
    asm volatile("mma.sync.aligned.m16n8k16.row.col.f32.f16.f16.f32 "
                 "{%0,%1,%2,%3}, {%4,%5,%6,%7}, {%8,%9}, {%0,%1,%2,%3};"
                 : "+f"(c[0]), "+f"(c[1]), "+f"(c[2]), "+f"(c[3])
                 : "r"(a0), "r"(a1), "r"(a2), "r"(a3), "r"(b0), "r"(b1));
}

// ---------------- prep: (optional gelu^2 + grouped) -> transpose -> fp16
template <typename T>
__global__ void __launch_bounds__(256) prep_k(const T* __restrict__ in,
                                              const float* __restrict__ wg,
                                              const float* __restrict__ bg,
                                              __half* __restrict__ out,
                                              float* __restrict__ ppart,
                                              double* __restrict__ part,
                                              int do_gelu) {
    extern __shared__ __align__(16) char sm[];
    char* ot = sm;                              // 64 px rows x 516 bytes = 33024
    float* sacc = (float*)(sm + 33024);         // 512 floats
    float* sf   = (float*)(sm + 35072);         // 512 floats (stats)
    int t = threadIdx.x;
    int b = blockIdx.y, pt = blockIdx.x;
    int p0 = pt * 64;
    int gq = t >> 6, pp = t & 63;
    size_t ibase = (size_t)b * CHW + p0 + pp;

    float fs = 0.f, fs2 = 0.f;
#pragma unroll 4
    for (int gi = 0; gi < 16; gi++) {
        int g = gq * 16 + gi;
        int c0 = g * 4;
        float v[4];
#pragma unroll
        for (int i = 0; i < 4; i++) {
            float x = (float)in[ibase + (size_t)(c0 + i) * HW];
            if (part) { fs += x; fs2 += x * x; }
            v[i] = do_gelu ? gelu1(gelu1(x)) : x;
        }
        float u[4];
        if (wg) {
#pragma unroll
            for (int o = 0; o < 4; o++) {
                float s = __ldg(&bg[c0 + o]);
#pragma unroll
                for (int i = 0; i < 4; i++) s += __ldg(&wg[g * 16 + o * 4 + i]) * v[i];
                u[o] = s;
            }
        } else {
#pragma unroll
            for (int o = 0; o < 4; o++) u[o] = v[o];
        }
#pragma unroll
        for (int o = 0; o < 4; o++) {
            int c = c0 + o;
            *(__half*)(ot + pp * 516 + c * 2) = __float2half(u[o]);
            if (ppart) {
                float s = u[o];
#pragma unroll
                for (int off = 16; off > 0; off >>= 1)
                    s += __shfl_down_sync(0xffffffffu, s, off);
                if ((t & 31) == 0) sacc[c * 2 + ((t >> 5) & 1)] = s;
            }
        }
    }
    __syncthreads();
    uint32_t* og = (uint32_t*)out;
#pragma unroll
    for (int it = 0; it < 32; it++) {
        int idx = it * 256 + t;
        int r = idx >> 7, ww = idx & 127;
        og[((size_t)b * HW + p0 + r) * 128 + ww] = *(uint32_t*)(ot + r * 516 + ww * 4);
    }
    if (ppart) {
        float s2 = sacc[t * 2] + sacc[t * 2 + 1];
        ppart[((size_t)b * Cc + t) * 256 + pt] = s2;
    }
    if (part) {
        sf[t] = fs; sf[256 + t] = fs2;
        __syncthreads();
        for (int off = 128; off > 0; off >>= 1) {
            if (t < off) { sf[t] += sf[t + off]; sf[256 + t] += sf[256 + t + off]; }
            __syncthreads();
        }
        if (t == 0) {
            part[((size_t)b * 256 + pt) * 2 + 0] = (double)sf[0];
            part[((size_t)b * 256 + pt) * 2 + 1] = (double)sf[256];
        }
    }
}

// ---------------- A prep with inline GN stats reduce ----------------
// scale/shift derived from 256 stats partials (per batch), reduced per block.
__global__ void __launch_bounds__(256) aprep_gn_k(const float* __restrict__ W,
                                                  const float* __restrict__ bias,
                                                  const double* __restrict__ part,
                                                  const float* __restrict__ gw,
                                                  const float* __restrict__ gb,
                                                  __half* __restrict__ A,
                                                  float* __restrict__ bias2) {
    int o = blockIdx.x, b = blockIdx.y, t = threadIdx.x;
    __shared__ double sd[512];
    __shared__ float smean, srstd;
    sd[t]       = part[(b * 256 + t) * 2 + 0];
    sd[256 + t] = part[(b * 256 + t) * 2 + 1];
    __syncthreads();
    for (int off = 128; off > 0; off >>= 1) {
        if (t < off) { sd[t] += sd[t + off]; sd[256 + t] += sd[256 + t + off]; }
        __syncthreads();
    }
    if (t == 0) {
        double m = sd[0] / (double)CHW;
        double v = sd[256] / (double)CHW - m * m;
        smean = (float)m;
        srstd = rsqrtf((float)v + 1e-5f);
    }
    __syncthreads();
    float sc = srstd * __ldg(&gw[t]);
    float sh = __ldg(&gb[t]) - smean * sc;

    float w = __ldg(&W[o * 256 + t]);
    A[((size_t)b * 256 + o) * 256 + t] = __float2half(w * sc);

    __shared__ float red[256];
    red[t] = w * sh;
    __syncthreads();
    for (int off = 128; off > 0; off >>= 1) {
        if (t < off) red[t] += red[t + off];
        __syncthreads();
    }
    if (t == 0) bias2[b * Cc + o] = __ldg(&bias[o]) + red[0];
}

// ---------------- A prep (plain / attention-scaled) ----------------
__global__ void __launch_bounds__(256) aprep_k(const float* __restrict__ W,
                                               const float* __restrict__ bias,
                                               const float* __restrict__ sc,
                                               __half* __restrict__ A,
                                               float* __restrict__ bias2) {
    int o = blockIdx.x, b = blockIdx.y, t = threadIdx.x;
    float w = __ldg(&W[o * 256 + t]);
    float s = sc ? w * sc[b * Cc + t] : w;
    A[((size_t)b * 256 + o) * 256 + t] = __float2half(s);
    if (t == 0) bias2[b * Cc + o] = __ldg(&bias[o]);
}

// ---------------- fp16 GEMM via mma.sync (K=256, 4 chunks) ----------------
// EPI 0: out fp16 CHW (no residual)
// EPI 1: z = y*echan + res; O16: z stored fp16, else fp32(__stcs); R16: res fp16
//        STAT: GN partials from fp32 z; XCOUT: transposed fp16 z
__device__ __forceinline__ void load_chunk(int i, int t, uint32_t sb,
                                           const __half* Ab, const __half* Bbp) {
    int col = i * 64;
    uint32_t abase = sb + (i % 3) * 32768;
    uint32_t bbase = abase + 16384;
    int row = t >> 3, k8 = t & 7;
#pragma unroll
    for (int j = 0; j < 4; j++) {
        int r = row + j * 32;
        CP_ASYNC16(abase + SWZ128(r * 128 + k8 * 16), Ab + (size_t)r * 256 + col + k8 * 8);
        CP_ASYNC16(bbase + SWZ128(r * 128 + k8 * 16), Bbp + (size_t)r * 256 + col + k8 * 8);
    }
}

template <int EPI, int STAT, int XCOUT, int O16, int R16>
__global__ void __launch_bounds__(256, 2) gemm_k(
    const __half* __restrict__ A, const __half* __restrict__ Xc,
    const float* __restrict__ bias2, void* __restrict__ outv,
    const float* __restrict__ echan, const void* __restrict__ resv,
    double* __restrict__ statp, __half* __restrict__ xcout) {

    extern __shared__ __align__(1024) char sm[];
    uint32_t sb = smem_u32(sm);
    int t = threadIdx.x, lane = t & 31, w = t >> 5;
    int wm = w >> 2, wn = w & 3;
    int o0 = blockIdx.x * 128, p0 = blockIdx.y * 128, b = blockIdx.z;
    const __half* Ab  = A  + ((size_t)b * 256 + o0) * 256;
    const __half* Bbp = Xc + ((size_t)b * HW  + p0) * 256;

    load_chunk(0, t, sb, Ab, Bbp); CP_COMMIT();
    load_chunk(1, t, sb, Ab, Bbp); CP_COMMIT();

    float acc[4][4][4];
#pragma unroll
    for (int mi = 0; mi < 4; mi++)
#pragma unroll
        for (int ni = 0; ni < 4; ni++)
#pragma unroll
            for (int q = 0; q < 4; q++) acc[mi][ni][q] = 0.f;

#pragma unroll
    for (int i = 0; i < 4; i++) {
        if (i == 3) { CP_WAIT0(); } else { CP_WAIT1(); }
        __syncthreads();
        if (i + 2 < 4) { load_chunk(i + 2, t, sb, Ab, Bbp); CP_COMMIT(); }

        uint32_t as = sb + (i % 3) * 32768, bs = as + 16384;
#pragma unroll
        for (int k2 = 0; k2 < 4; k2++) {
            uint32_t a[4][4];
#pragma unroll
            for (int mi = 0; mi < 4; mi++) {
                int r  = wm * 64 + mi * 16 + (lane & 15);
                int ch = k2 * 2 + (lane >> 4);
                ldsm4(a[mi][0], a[mi][1], a[mi][2], a[mi][3],
                      as + r * 128 + ((ch ^ (r & 7)) * 16));
            }
            uint32_t bb[2][4];
#pragma unroll
            for (int h = 0; h < 2; h++) {
                int r  = wn * 32 + h * 16 + ((lane >> 4) & 1) * 8 + (lane & 7);
                int ch = k2 * 2 + ((lane >> 3) & 1);
                ldsm4(bb[h][0], bb[h][1], bb[h][2], bb[h][3],
                      bs + r * 128 + ((ch ^ (r & 7)) * 16));
            }
#pragma unroll
            for (int mi = 0; mi < 4; mi++)
#pragma unroll
                for (int ni = 0; ni < 4; ni++) {
                    int h = ni >> 1, q = (ni & 1) * 2;
                    mma16816(acc[mi][ni], a[mi][0], a[mi][1], a[mi][2], a[mi][3],
                             bb[h][q], bb[h][q + 1]);
                }
        }
        __syncthreads();
    }

    int g = lane >> 2, i4 = lane & 3;
    char*  st16 = sm;                    // XCOUT staging: [128 p][260 B] = 33280
    float* sf   = (float*)(sm + 34816);  // STAT staging: 512 floats
    float ls = 0.f, ls2 = 0.f;
#pragma unroll
    for (int mi = 0; mi < 4; mi++) {
        int o = o0 + wm * 64 + mi * 16 + g;
        int ol = wm * 64 + mi * 16 + g;
        float bv0 = bias2[b * Cc + o], bv1 = bias2[b * Cc + o + 8];
        float e0 = 1.f, e1 = 1.f;
        if (EPI) { e0 = __ldg(&echan[o]); e1 = __ldg(&echan[o + 8]); }
        size_t r0b = (size_t)b * CHW + (size_t)o * HW;
        size_t r1b = r0b + (size_t)8 * HW;
#pragma unroll
        for (int ni = 0; ni < 4; ni++) {
            int pl = wn * 32 + ni * 8 + i4 * 2;
            int p = p0 + pl;
            float y00 = acc[mi][ni][0] + bv0, y01 = acc[mi][ni][1] + bv0;
            float y10 = acc[mi][ni][2] + bv1, y11 = acc[mi][ni][3] + bv1;
            if (EPI) {
                float2 q0, q1;
                if (R16) {
                    const __half* res = (const __half*)resv;
                    __half2 h0 = __ldcs((const __half2*)(res + r0b + p));
                    __half2 h1 = __ldcs((const __half2*)(res + r1b + p));
                    q0 = __half22float2(h0); q1 = __half22float2(h1);
                } else {
                    const float* res = (const float*)resv;
                    q0 = __ldcs((const float2*)(res + r0b + p));
                    q1 = __ldcs((const float2*)(res + r1b + p));
                }
                float2 z0, z1;
                z0.x = y00 * e0 + q0.x; z0.y = y01 * e0 + q0.y;
                z1.x = y10 * e1 + q1.x; z1.y = y11 * e1 + q1.y;
                if (O16) {
                    __half* out = (__half*)outv;
                    __half2 h0, h1;
                    h0.x = __float2half(z0.x); h0.y = __float2half(z0.y);
                    h1.x = __float2half(z1.x); h1.y = __float2half(z1.y);
                    __stcs((__half2*)(out + r0b + p), h0);
                    __stcs((__half2*)(out + r1b + p), h1);
                } else {
                    float* out = (float*)outv;
                    __stcs((float2*)(out + r0b + p), z0);
                    __stcs((float2*)(out + r1b + p), z1);
                }
                if (STAT) {
                    ls  += z0.x + z0.y + z1.x + z1.y;
                    ls2 += z0.x * z0.x + z0.y * z0.y + z1.x * z1.x + z1.y * z1.y;
                }
                if (XCOUT) {
                    *(__half*)(st16 + (pl)     * 260 + ol * 2)       = __float2half(z0.x);
                    *(__half*)(st16 + (pl + 1) * 260 + ol * 2)       = __float2half(z0.y);
                    *(__half*)(st16 + (pl)     * 260 + (ol + 8) * 2) = __float2half(z1.x);
                    *(__half*)(st16 + (pl + 1) * 260 + (ol + 8) * 2) = __float2half(z1.y);
                }
            } else {
                __half* out = (__half*)outv;
                __half2 h0, h1;
                h0.x = __float2half(y00); h0.y = __float2half(y01);
                h1.x = __float2half(y10); h1.y = __float2half(y11);
                *(__half2*)(out + r0b + p) = h0;
                *(__half2*)(out + r1b + p) = h1;
            }
        }
    }

    if (XCOUT) {
        __syncthreads();
        uint32_t* og = (uint32_t*)xcout;
#pragma unroll
        for (int it = 0; it < 32; it++) {
            int idx = it * 256 + t;
            int r = idx >> 6, ww = idx & 63;
            og[((size_t)b * HW + p0 + r) * 128 + (o0 >> 1) + ww] =
                *(uint32_t*)(st16 + r * 260 + ww * 4);
        }
    }

    if (STAT) {
        sf[t] = ls; sf[256 + t] = ls2;
        __syncthreads();
        for (int off = 128; off > 0; off >>= 1) {
            if (t < off) { sf[t] += sf[t + off]; sf[256 + t] += sf[256 + t + off]; }
            __syncthreads();
        }
        if (t == 0) {
            int idx = blockIdx.x + 2 * blockIdx.y;
            statp[((size_t)b * 256 + idx) * 2 + 0] = (double)sf[0];
            statp[((size_t)b * 256 + idx) * 2 + 1] = (double)sf[256];
        }
    }
}

// ---------------- depthwise 3x3 (fp16 in/out, fp32 math) ----------------
__global__ void __launch_bounds__(256) dw3x3_k(const __half* __restrict__ in,
                                               const float* __restrict__ w2,
                                               const float* __restrict__ b2,
                                               __half* __restrict__ out) {
    __shared__ float s[34][128];
    int t = threadIdx.x;
    int b = blockIdx.z, c = blockIdx.y;
    int r0 = blockIdx.x * 32;
    size_t base = (size_t)b * CHW + (size_t)c * HW;
#pragma unroll
    for (int it = 0; it < 17; it++) {
        int idx = it * 256 + t;
        int rr = idx >> 7, cc = idx & 127;
        int gr = r0 - 1 + rr;
        s[rr][cc] = (gr >= 0 && gr < Hh) ? __half2float(in[base + (size_t)gr * Wwid + cc]) : 0.f;
    }
    float wv[9];
#pragma unroll
    for (int i = 0; i < 9; i++) wv[i] = __ldg(&w2[c * 9 + i]);
    float bias = __ldg(&b2[c]);
    __syncthreads();
#pragma unroll
    for (int it = 0; it < 16; it++) {
        int idx = it * 256 + t;
        int r = idx >> 7, cc = idx & 127;
        int sr = r + 1;
        float sum = bias;
#pragma unroll
        for (int dy = 0; dy < 3; dy++) {
            float l = (cc > 0)   ? s[sr - 1 + dy][cc - 1] : 0.f;
            float m = s[sr - 1 + dy][cc];
            float rr = (cc < 127) ? s[sr - 1 + dy][cc + 1] : 0.f;
            sum += wv[dy * 3 + 0] * l + wv[dy * 3 + 1] * m + wv[dy * 3 + 2] * rr;
        }
        out[base + (size_t)(r0 + r) * Wwid + cc] = __float2half(sum);
    }
}

// ---------------- channel attention ----------------
__global__ void __launch_bounds__(256) att_k(const float* __restrict__ ppart,
                                             const float* __restrict__ wsca,
                                             const float* __restrict__ bsca,
                                             float* __restrict__ att) {
    __shared__ float sp[256];
    int b = blockIdx.x, t = threadIdx.x;
    float s = 0.f;
    const float* pr = ppart + ((size_t)b * Cc + t) * 256;
#pragma unroll 8
    for (int j = 0; j < 256; j++) s += pr[j];
    sp[t] = s * (1.f / (float)HW);
    __syncthreads();
    float acc = __ldg(&bsca[t]);
    const float* wrow = wsca + (size_t)t * 256;
#pragma unroll 8
    for (int c = 0; c < 256; c++) acc += sp[c] * __ldg(&wrow[c]);
    att[b * Cc + t] = acc;
}

// ---------------- launch ----------------
extern "C" void kernel_launch(void* const* d_in, const int* in_sizes, int n_in,
                              void* d_out, int out_size) {
    const float* x     = (const float*)d_in[0];
    const float* gn1_w = (const float*)d_in[1];
    const float* gn1_b = (const float*)d_in[2];
    const float* w1    = (const float*)d_in[3];
    const float* b1    = (const float*)d_in[4];
    const float* w2    = (const float*)d_in[5];
    const float* b2    = (const float*)d_in[6];
    const float* wg1   = (const float*)d_in[7];
    const float* bg1   = (const float*)d_in[8];
    const float* w_sca = (const float*)d_in[9];
    const float* b_sca = (const float*)d_in[10];
    const float* w3    = (const float*)d_in[11];
    const float* b3    = (const float*)d_in[12];
    const float* gn2_w = (const float*)d_in[13];
    const float* gn2_b = (const float*)d_in[14];
    const float* w4    = (const float*)d_in[15];
    const float* b4    = (const float*)d_in[16];
    const float* wg2   = (const float*)d_in[17];
    const float* bg2   = (const float*)d_in[18];
    const float* w5    = (const float*)d_in[19];
    const float* b5    = (const float*)d_in[20];
    const float* beta  = (const float*)d_in[21];
    const float* gamma = (const float*)d_in[22];
    float* out = (float*)d_out;

    float *ppart, *attv, *bias2;
    __half *bufAh, *bufBh, *bufX1h, *XcA, *XcB, *Abuf;
    double *part, *part2;
    cudaGetSymbolAddress((void**)&bufAh,  g_bufAh);
    cudaGetSymbolAddress((void**)&bufBh,  g_bufBh);
    cudaGetSymbolAddress((void**)&bufX1h, g_bufX1h);
    cudaGetSymbolAddress((void**)&XcA,    g_XcA);
    cudaGetSymbolAddress((void**)&XcB,    g_XcB);
    cudaGetSymbolAddress((void**)&Abuf,   g_Abuf);
    cudaGetSymbolAddress((void**)&bias2,  g_bias2);
    cudaGetSymbolAddress((void**)&part,   g_part);
    cudaGetSymbolAddress((void**)&part2,  g_part2);
    cudaGetSymbolAddress((void**)&ppart,  g_ppart);
    cudaGetSymbolAddress((void**)&attv,   g_att);

    const int GEMM_SMEM = 3 * 32768;
    const int PREP_SMEM = 33024 + 2048 + 2048;
    cudaFuncSetAttribute((const void*)gemm_k<0,0,0,0,0>, cudaFuncAttributeMaxDynamicSharedMemorySize, GEMM_SMEM);
    cudaFuncSetAttribute((const void*)gemm_k<1,1,1,1,0>, cudaFuncAttributeMaxDynamicSharedMemorySize, GEMM_SMEM);
    cudaFuncSetAttribute((const void*)gemm_k<1,0,0,0,1>, cudaFuncAttributeMaxDynamicSharedMemorySize, GEMM_SMEM);
    cudaFuncSetAttribute((const void*)prep_k<float>,  cudaFuncAttributeMaxDynamicSharedMemorySize, PREP_SMEM);
    cudaFuncSetAttribute((const void*)prep_k<__half>, cudaFuncAttributeMaxDynamicSharedMemorySize, PREP_SMEM);

    dim3 ggrid(2, 128, Bb);
    dim3 pgrid(256, Bb);
    dim3 agrid(256, Bb);
    dim3 dgrid(4, Cc, Bb);

    // ---- path 1 ----
    prep_k<float><<<pgrid, 256, PREP_SMEM>>>(x, nullptr, nullptr, XcA, nullptr, part, 0);
    aprep_gn_k<<<agrid, 256>>>(w1, b1, part, gn1_w, gn1_b, Abuf, bias2);
    gemm_k<0,0,0,0,0><<<ggrid, 256, GEMM_SMEM>>>(Abuf, XcA, bias2, bufAh,
                                                 nullptr, nullptr, nullptr, nullptr);
    dw3x3_k<<<dgrid, 256>>>(bufAh, w2, b2, bufBh);
    prep_k<__half><<<pgrid, 256, PREP_SMEM>>>(bufBh, wg1, bg1, XcB, ppart, nullptr, 1);
    att_k<<<Bb, 256>>>(ppart, w_sca, b_sca, attv);
    aprep_k<<<agrid, 256>>>(w3, b3, attv, Abuf, bias2);
    // x1 = y*beta + x -> bufX1h (fp16) ; + XcA (fp16 transposed) ; + GN2 partials
    gemm_k<1,1,1,1,0><<<ggrid, 256, GEMM_SMEM>>>(Abuf, XcB, bias2, bufX1h,
                                                 beta, x, part2, XcA);

    // ---- path 2 ----
    aprep_gn_k<<<agrid, 256>>>(w4, b4, part2, gn2_w, gn2_b, Abuf, bias2);
    gemm_k<0,0,0,0,0><<<ggrid, 256, GEMM_SMEM>>>(Abuf, XcA, bias2, bufAh,
                                                 nullptr, nullptr, nullptr, nullptr);
    prep_k<__half><<<pgrid, 256, PREP_SMEM>>>(bufAh, wg2, bg2, XcB, nullptr, nullptr, 1);
    aprep_k<<<agrid, 256>>>(w5, b5, nullptr, Abuf, bias2);
    gemm_k<1,0,0,0,1><<<ggrid, 256, GEMM_SMEM>>>(Abuf, XcB, bias2, out,
                                                 gamma, bufX1h, nullptr, nullptr);
}

// round 13
// speedup vs baseline: 1.0362x; 1.0362x over previous
#include <cuda_runtime.h>
#include <cuda_fp16.h>
#include <math.h>
#include <stdint.h>

#define Cc   256
#define Hh   128
#define Wwid 128
#define HW   16384
#define CHW  4194304
#define Bb   8

// ---------------- static scratch ----------------
__device__ __align__(1024) __half g_bufAh[(size_t)Bb * CHW];   // conv1/conv4 out (fp16)
__device__ __align__(1024) __half g_bufBh[(size_t)Bb * CHW];   // dw3x3 out (fp16)
__device__ __align__(1024) float  g_bufX1[(size_t)Bb * CHW];   // x1 residual (fp32)
__device__ __align__(1024) __half g_XcA[(size_t)Bb * HW * 256]; // B operand fp16
__device__ __align__(1024) __half g_XcB[(size_t)Bb * HW * 256];
__device__ __align__(1024) __half g_Abuf[(size_t)Bb * 256 * 256]; // A fp16
__device__ float  g_bias2[Bb * Cc];
__device__ double g_part[Bb * 256 * 2];      // GN1 partials (from prep1)
__device__ double g_part2[Bb * 256 * 2];     // GN2 partials (from gemm3 epilogue)
__device__ float  g_ppart[(size_t)Bb * Cc * 256];
__device__ float  g_scale[Bb * Cc];
__device__ float  g_shift[Bb * Cc];
__device__ float  g_att[Bb * Cc];

__device__ __forceinline__ float gelu1(float x) {
    return 0.5f * x * (1.0f + erff(x * 0.70710678118654752440f));
}

// ---------------- PTX helpers ----------------
__device__ __forceinline__ uint32_t smem_u32(const void* p) {
    uint32_t a;
    asm("{ .reg .u64 t; cvta.to.shared.u64 t, %1; cvt.u32.u64 %0, t; }" : "=r"(a) : "l"(p));
    return a;
}
#define SWZ128(off) ((off) ^ (((off) >> 3) & 0x70))
#define CP_ASYNC16(sa, g) asm volatile("cp.async.cg.shared.global [%0], [%1], 16;" :: "r"(sa), "l"(g) : "memory")
#define CP_COMMIT() asm volatile("cp.async.commit_group;" ::: "memory")
#define CP_WAIT1()  asm volatile("cp.async.wait_group 1;" ::: "memory")
#define CP_WAIT0()  asm volatile("cp.async.wait_group 0;" ::: "memory")

__device__ __forceinline__ void ldsm4(uint32_t& r0, uint32_t& r1, uint32_t& r2, uint32_t& r3,
                                      uint32_t a) {
    asm volatile("ldmatrix.sync.aligned.m8n8.x4.shared.b16 {%0,%1,%2,%3}, [%4];"
                 : "=r"(r0), "=r"(r1), "=r"(r2), "=r"(r3) : "r"(a));
}
__device__ __forceinline__ void mma16816(float* c, uint32_t a0, uint32_t a1, uint32_t a2,
                                         uint32_t a3, uint32_t b0, uint32_t b1) {
    asm volatile("mma.sync.aligned.m16n8k16.row.col.f32.f16.f16.f32 "
                 "{%0,%1,%2,%3}, {%4,%5,%6,%7}, {%8,%9}, {%0,%1,%2,%3};"
                 : "+f"(c[0]), "+f"(c[1]), "+f"(c[2]), "+f"(c[3])
                 : "r"(a0), "r"(a1), "r"(a2), "r"(a3), "r"(b0), "r"(b1));
}

// ---------------- stats reduce: 256 partials per batch -> scale/shift --------
__global__ void __launch_bounds__(256) stats2_k(const double* __restrict__ part,
                                                const float* __restrict__ gw,
                                                const float* __restrict__ gb,
                                                float* __restrict__ scale,
                                                float* __restrict__ shift) {
    int b = blockIdx.x, t = threadIdx.x;
    __shared__ double ss[256], ss2[256];
    __shared__ float smean, srstd;
    ss[t]  = part[(b * 256 + t) * 2 + 0];
    ss2[t] = part[(b * 256 + t) * 2 + 1];
    __syncthreads();
    for (int off = 128; off > 0; off >>= 1) {
        if (t < off) { ss[t] += ss[t + off]; ss2[t] += ss2[t + off]; }
        __syncthreads();
    }
    if (t == 0) {
        double m = ss[0] / (double)CHW;
        double v = ss2[0] / (double)CHW - m * m;
        smean = (float)m;
        srstd = rsqrtf((float)v + 1e-5f);
    }
    __syncthreads();
    float sc = srstd * gw[t];
    scale[b * Cc + t] = sc;
    shift[b * Cc + t] = gb[t] - smean * sc;
}

// ---------------- prep: (optional gelu^2 + grouped) -> transpose -> fp16
template <typename T>
__global__ void __launch_bounds__(256) prep_k(const T* __restrict__ in,
                                              const float* __restrict__ wg,
                                              const float* __restrict__ bg,
                                              __half* __restrict__ out,
                                              float* __restrict__ ppart,
                                              double* __restrict__ part,
                                              int do_gelu) {
    extern __shared__ __align__(16) char sm[];
    char* ot = sm;                              // 64 px rows x 516 bytes = 33024
    float* sacc = (float*)(sm + 33024);         // 512 floats
    float* sf   = (float*)(sm + 35072);         // 512 floats (stats)
    int t = threadIdx.x;
    int b = blockIdx.y, pt = blockIdx.x;
    int p0 = pt * 64;
    int gq = t >> 6, pp = t & 63;
    size_t ibase = (size_t)b * CHW + p0 + pp;

    float fs = 0.f, fs2 = 0.f;
#pragma unroll 4
    for (int gi = 0; gi < 16; gi++) {
        int g = gq * 16 + gi;
        int c0 = g * 4;
        float v[4];
#pragma unroll
        for (int i = 0; i < 4; i++) {
            float x = (float)in[ibase + (size_t)(c0 + i) * HW];
            if (part) { fs += x; fs2 += x * x; }
            v[i] = do_gelu ? gelu1(gelu1(x)) : x;
        }
        float u[4];
        if (wg) {
#pragma unroll
            for (int o = 0; o < 4; o++) {
                float s = __ldg(&bg[c0 + o]);
#pragma unroll
                for (int i = 0; i < 4; i++) s += __ldg(&wg[g * 16 + o * 4 + i]) * v[i];
                u[o] = s;
            }
        } else {
#pragma unroll
            for (int o = 0; o < 4; o++) u[o] = v[o];
        }
#pragma unroll
        for (int o = 0; o < 4; o++) {
            int c = c0 + o;
            *(__half*)(ot + pp * 516 + c * 2) = __float2half(u[o]);
            if (ppart) {
                float s = u[o];
#pragma unroll
                for (int off = 16; off > 0; off >>= 1)
                    s += __shfl_down_sync(0xffffffffu, s, off);
                if ((t & 31) == 0) sacc[c * 2 + ((t >> 5) & 1)] = s;
            }
        }
    }
    __syncthreads();
    uint32_t* og = (uint32_t*)out;
#pragma unroll
    for (int it = 0; it < 32; it++) {
        int idx = it * 256 + t;
        int r = idx >> 7, ww = idx & 127;
        og[((size_t)b * HW + p0 + r) * 128 + ww] = *(uint32_t*)(ot + r * 516 + ww * 4);
    }
    if (ppart) {
        float s2 = sacc[t * 2] + sacc[t * 2 + 1];
        ppart[((size_t)b * Cc + t) * 256 + pt] = s2;
    }
    if (part) {
        sf[t] = fs; sf[256 + t] = fs2;
        __syncthreads();
        for (int off = 128; off > 0; off >>= 1) {
            if (t < off) { sf[t] += sf[t + off]; sf[256 + t] += sf[256 + t + off]; }
            __syncthreads();
        }
        if (t == 0) {
            part[((size_t)b * 256 + pt) * 2 + 0] = (double)sf[0];
            part[((size_t)b * 256 + pt) * 2 + 1] = (double)sf[256];
        }
    }
}

// ---------------- A prep ----------------
__global__ void __launch_bounds__(256) aprep_k(const float* __restrict__ W,
                                               const float* __restrict__ bias,
                                               const float* __restrict__ sc,
                                               const float* __restrict__ sh,
                                               __half* __restrict__ A,
                                               float* __restrict__ bias2) {
    int o = blockIdx.x, b = blockIdx.y, t = threadIdx.x;
    float w = __ldg(&W[o * 256 + t]);
    float s = sc ? w * sc[b * Cc + t] : w;
    A[((size_t)b * 256 + o) * 256 + t] = __float2half(s);

    __shared__ float red[256];
    red[t] = sh ? w * sh[b * Cc + t] : 0.f;
    __syncthreads();
    for (int off = 128; off > 0; off >>= 1) {
        if (t < off) red[t] += red[t + off];
        __syncthreads();
    }
    if (t == 0) bias2[b * Cc + o] = __ldg(&bias[o]) + red[0];
}

// ---------------- fp16 GEMM via mma.sync (K=256, 4 chunks) ----------------
// EPI 0: out fp16 CHW
// EPI 1: z = y*echan + res -> fp32 CHW (STAT: + GN partials; XCOUT: + transposed fp16)
__device__ __forceinline__ void load_chunk(int i, int t, uint32_t sb,
                                           const __half* Ab, const __half* Bbp) {
    int col = i * 64;
    uint32_t abase = sb + (i % 3) * 32768;
    uint32_t bbase = abase + 16384;
    int row = t >> 3, k8 = t & 7;
#pragma unroll
    for (int j = 0; j < 4; j++) {
        int r = row + j * 32;
        CP_ASYNC16(abase + SWZ128(r * 128 + k8 * 16), Ab + (size_t)r * 256 + col + k8 * 8);
        CP_ASYNC16(bbase + SWZ128(r * 128 + k8 * 16), Bbp + (size_t)r * 256 + col + k8 * 8);
    }
}

template <int EPI, int STAT, int XCOUT>
__global__ void __launch_bounds__(256, 2) gemm_k(
    const __half* __restrict__ A, const __half* __restrict__ Xc,
    const float* __restrict__ bias2, void* __restrict__ outv,
    const float* __restrict__ echan, const float* __restrict__ res,
    double* __restrict__ statp, __half* __restrict__ xcout) {

    extern __shared__ __align__(1024) char sm[];
    uint32_t sb = smem_u32(sm);
    int t = threadIdx.x, lane = t & 31, w = t >> 5;
    int wm = w >> 2, wn = w & 3;
    int o0 = blockIdx.x * 128, p0 = blockIdx.y * 128, b = blockIdx.z;
    const __half* Ab  = A  + ((size_t)b * 256 + o0) * 256;
    const __half* Bbp = Xc + ((size_t)b * HW  + p0) * 256;

    load_chunk(0, t, sb, Ab, Bbp); CP_COMMIT();
    load_chunk(1, t, sb, Ab, Bbp); CP_COMMIT();

    float acc[4][4][4];
#pragma unroll
    for (int mi = 0; mi < 4; mi++)
#pragma unroll
        for (int ni = 0; ni < 4; ni++)
#pragma unroll
            for (int q = 0; q < 4; q++) acc[mi][ni][q] = 0.f;

#pragma unroll
    for (int i = 0; i < 4; i++) {
        if (i == 3) { CP_WAIT0(); } else { CP_WAIT1(); }
        __syncthreads();
        if (i + 2 < 4) { load_chunk(i + 2, t, sb, Ab, Bbp); CP_COMMIT(); }

        uint32_t as = sb + (i % 3) * 32768, bs = as + 16384;
#pragma unroll
        for (int k2 = 0; k2 < 4; k2++) {
            uint32_t a[4][4];
#pragma unroll
            for (int mi = 0; mi < 4; mi++) {
                int r  = wm * 64 + mi * 16 + (lane & 15);
                int ch = k2 * 2 + (lane >> 4);
                ldsm4(a[mi][0], a[mi][1], a[mi][2], a[mi][3],
                      as + r * 128 + ((ch ^ (r & 7)) * 16));
            }
            uint32_t bb[2][4];
#pragma unroll
            for (int h = 0; h < 2; h++) {
                int r  = wn * 32 + h * 16 + ((lane >> 4) & 1) * 8 + (lane & 7);
                int ch = k2 * 2 + ((lane >> 3) & 1);
                ldsm4(bb[h][0], bb[h][1], bb[h][2], bb[h][3],
                      bs + r * 128 + ((ch ^ (r & 7)) * 16));
            }
#pragma unroll
            for (int mi = 0; mi < 4; mi++)
#pragma unroll
                for (int ni = 0; ni < 4; ni++) {
                    int h = ni >> 1, q = (ni & 1) * 2;
                    mma16816(acc[mi][ni], a[mi][0], a[mi][1], a[mi][2], a[mi][3],
                             bb[h][q], bb[h][q + 1]);
                }
        }
        __syncthreads();
    }

    int g = lane >> 2, i4 = lane & 3;
    char*  st16 = sm;                    // XCOUT staging: [128 p][260 B] = 33280
    float* sf   = (float*)(sm + 34816);  // STAT staging: 512 floats
    float ls = 0.f, ls2 = 0.f;
#pragma unroll
    for (int mi = 0; mi < 4; mi++) {
        int o = o0 + wm * 64 + mi * 16 + g;
        int ol = wm * 64 + mi * 16 + g;
        float bv0 = bias2[b * Cc + o], bv1 = bias2[b * Cc + o + 8];
        float e0 = 1.f, e1 = 1.f;
        if (EPI) { e0 = __ldg(&echan[o]); e1 = __ldg(&echan[o + 8]); }
        size_t r0b = (size_t)b * CHW + (size_t)o * HW;
        size_t r1b = r0b + (size_t)8 * HW;
#pragma unroll
        for (int ni = 0; ni < 4; ni++) {
            int pl = wn * 32 + ni * 8 + i4 * 2;
            int p = p0 + pl;
            float y00 = acc[mi][ni][0] + bv0, y01 = acc[mi][ni][1] + bv0;
            float y10 = acc[mi][ni][2] + bv1, y11 = acc[mi][ni][3] + bv1;
            if (EPI) {
                float* out = (float*)outv;
                float2 q0 = __ldcs((const float2*)(res + r0b + p));
                float2 q1 = __ldcs((const float2*)(res + r1b + p));
                float2 z0, z1;
                z0.x = y00 * e0 + q0.x; z0.y = y01 * e0 + q0.y;
                z1.x = y10 * e1 + q1.x; z1.y = y11 * e1 + q1.y;
                __stcs((float2*)(out + r0b + p), z0);
                __stcs((float2*)(out + r1b + p), z1);
                if (STAT) {
                    ls  += z0.x + z0.y + z1.x + z1.y;
                    ls2 += z0.x * z0.x + z0.y * z0.y + z1.x * z1.x + z1.y * z1.y;
                }
                if (XCOUT) {
                    *(__half*)(st16 + (pl)     * 260 + ol * 2)       = __float2half(z0.x);
                    *(__half*)(st16 + (pl + 1) * 260 + ol * 2)       = __float2half(z0.y);
                    *(__half*)(st16 + (pl)     * 260 + (ol + 8) * 2) = __float2half(z1.x);
                    *(__half*)(st16 + (pl + 1) * 260 + (ol + 8) * 2) = __float2half(z1.y);
                }
            } else {
                __half* out = (__half*)outv;
                __half2 h0, h1;
                h0.x = __float2half(y00); h0.y = __float2half(y01);
                h1.x = __float2half(y10); h1.y = __float2half(y11);
                *(__half2*)(out + r0b + p) = h0;
                *(__half2*)(out + r1b + p) = h1;
            }
        }
    }

    if (XCOUT) {
        __syncthreads();
        uint32_t* og = (uint32_t*)xcout;
#pragma unroll
        for (int it = 0; it < 32; it++) {
            int idx = it * 256 + t;
            int r = idx >> 6, ww = idx & 63;
            og[((size_t)b * HW + p0 + r) * 128 + (o0 >> 1) + ww] =
                *(uint32_t*)(st16 + r * 260 + ww * 4);
        }
    }

    if (STAT) {
        sf[t] = ls; sf[256 + t] = ls2;
        __syncthreads();
        for (int off = 128; off > 0; off >>= 1) {
            if (t < off) { sf[t] += sf[t + off]; sf[256 + t] += sf[256 + t + off]; }
            __syncthreads();
        }
        if (t == 0) {
            int idx = blockIdx.x + 2 * blockIdx.y;
            statp[((size_t)b * 256 + idx) * 2 + 0] = (double)sf[0];
            statp[((size_t)b * 256 + idx) * 2 + 1] = (double)sf[256];
        }
    }
}

// ---------------- depthwise 3x3: padded smem + 4px/thread vectorized ----------
__global__ void __launch_bounds__(256) dw3x3_k(const __half* __restrict__ in,
                                               const float* __restrict__ w2,
                                               const float* __restrict__ b2,
                                               __half* __restrict__ out) {
    __shared__ float s[34][132];   // halo cols: [0] and [129..131] zero; data at +1
    int t = threadIdx.x;
    int b = blockIdx.z, c = blockIdx.y;
    int r0 = blockIdx.x * 32;
    size_t base = (size_t)b * CHW + (size_t)c * HW;

    if (t < 34) { s[t][0] = 0.f; s[t][129] = 0.f; s[t][130] = 0.f; s[t][131] = 0.f; }
#pragma unroll
    for (int it = 0; it < 17; it++) {
        int idx = it * 256 + t;
        int rr = idx >> 7, cc = idx & 127;
        int gr = r0 - 1 + rr;
        s[rr][cc + 1] = (gr >= 0 && gr < Hh) ? __half2float(in[base + (size_t)gr * Wwid + cc]) : 0.f;
    }
    float wv[9];
#pragma unroll
    for (int i = 0; i < 9; i++) wv[i] = __ldg(&w2[c * 9 + i]);
    float bias = __ldg(&b2[c]);
    __syncthreads();

    int tc = (t & 31) * 4;   // output col group (0..124)
    int tr = t >> 5;         // row 0..7 within pass
#pragma unroll
    for (int rb = 0; rb < 4; rb++) {
        int r = rb * 8 + tr;
        int sr = r + 1;
        float a0 = bias, a1 = bias, a2 = bias, a3 = bias;
#pragma unroll
        for (int dy = 0; dy < 3; dy++) {
            const float* row = &s[sr - 1 + dy][tc];  // padded cols tc..tc+5
            float4 va = *(const float4*)(row);
            float2 vb = *(const float2*)(row + 4);
            float w0 = wv[dy * 3 + 0], w1 = wv[dy * 3 + 1], w2v = wv[dy * 3 + 2];
            a0 += w0 * va.x + w1 * va.y + w2v * va.z;
            a1 += w0 * va.y + w1 * va.z + w2v * va.w;
            a2 += w0 * va.z + w1 * va.w + w2v * vb.x;
            a3 += w0 * va.w + w1 * vb.x + w2v * vb.y;
        }
        __half2 h0, h1;
        h0.x = __float2half(a0); h0.y = __float2half(a1);
        h1.x = __float2half(a2); h1.y = __float2half(a3);
        __half2* op = (__half2*)(out + base + (size_t)(r0 + r) * Wwid + tc);
        op[0] = h0; op[1] = h1;
    }
}

// ---------------- channel attention ----------------
__global__ void __launch_bounds__(256) att_k(const float* __restrict__ ppart,
                                             const float* __restrict__ wsca,
                                             const float* __restrict__ bsca,
                                             float* __restrict__ att) {
    __shared__ float sp[256];
    int b = blockIdx.x, t = threadIdx.x;
    float s = 0.f;
    const float* pr = ppart + ((size_t)b * Cc + t) * 256;
#pragma unroll 8
    for (int j = 0; j < 256; j++) s += pr[j];
    sp[t] = s * (1.f / (float)HW);
    __syncthreads();
    float acc = __ldg(&bsca[t]);
    const float* wrow = wsca + (size_t)t * 256;
#pragma unroll 8
    for (int c = 0; c < 256; c++) acc += sp[c] * __ldg(&wrow[c]);
    att[b * Cc + t] = acc;
}

// ---------------- launch ----------------
extern "C" void kernel_launch(void* const* d_in, const int* in_sizes, int n_in,
                              void* d_out, int out_size) {
    const float* x     = (const float*)d_in[0];
    const float* gn1_w = (const float*)d_in[1];
    const float* gn1_b = (const float*)d_in[2];
    const float* w1    = (const float*)d_in[3];
    const float* b1    = (const float*)d_in[4];
    const float* w2    = (const float*)d_in[5];
    const float* b2    = (const float*)d_in[6];
    const float* wg1   = (const float*)d_in[7];
    const float* bg1   = (const float*)d_in[8];
    const float* w_sca = (const float*)d_in[9];
    const float* b_sca = (const float*)d_in[10];
    const float* w3    = (const float*)d_in[11];
    const float* b3    = (const float*)d_in[12];
    const float* gn2_w = (const float*)d_in[13];
    const float* gn2_b = (const float*)d_in[14];
    const float* w4    = (const float*)d_in[15];
    const float* b4    = (const float*)d_in[16];
    const float* wg2   = (const float*)d_in[17];
    const float* bg2   = (const float*)d_in[18];
    const float* w5    = (const float*)d_in[19];
    const float* b5    = (const float*)d_in[20];
    const float* beta  = (const float*)d_in[21];
    const float* gamma = (const float*)d_in[22];
    float* out = (float*)d_out;

    float *bufX1, *ppart, *scl, *shf, *attv, *bias2;
    __half *bufAh, *bufBh, *XcA, *XcB, *Abuf;
    double *part, *part2;
    cudaGetSymbolAddress((void**)&bufAh, g_bufAh);
    cudaGetSymbolAddress((void**)&bufBh, g_bufBh);
    cudaGetSymbolAddress((void**)&bufX1, g_bufX1);
    cudaGetSymbolAddress((void**)&XcA,   g_XcA);
    cudaGetSymbolAddress((void**)&XcB,   g_XcB);
    cudaGetSymbolAddress((void**)&Abuf,  g_Abuf);
    cudaGetSymbolAddress((void**)&bias2, g_bias2);
    cudaGetSymbolAddress((void**)&part,  g_part);
    cudaGetSymbolAddress((void**)&part2, g_part2);
    cudaGetSymbolAddress((void**)&ppart, g_ppart);
    cudaGetSymbolAddress((void**)&scl,   g_scale);
    cudaGetSymbolAddress((void**)&shf,   g_shift);
    cudaGetSymbolAddress((void**)&attv,  g_att);

    const int GEMM_SMEM = 3 * 32768;
    const int PREP_SMEM = 33024 + 2048 + 2048;
    cudaFuncSetAttribute(gemm_k<0,0,0>, cudaFuncAttributeMaxDynamicSharedMemorySize, GEMM_SMEM);
    cudaFuncSetAttribute(gemm_k<1,0,0>, cudaFuncAttributeMaxDynamicSharedMemorySize, GEMM_SMEM);
    cudaFuncSetAttribute(gemm_k<1,1,1>, cudaFuncAttributeMaxDynamicSharedMemorySize, GEMM_SMEM);
    cudaFuncSetAttribute(prep_k<float>,  cudaFuncAttributeMaxDynamicSharedMemorySize, PREP_SMEM);
    cudaFuncSetAttribute(prep_k<__half>, cudaFuncAttributeMaxDynamicSharedMemorySize, PREP_SMEM);

    dim3 ggrid(2, 128, Bb);
    dim3 pgrid(256, Bb);
    dim3 agrid(256, Bb);
    dim3 dgrid(4, Cc, Bb);

    // ---- path 1 ----
    prep_k<float><<<pgrid, 256, PREP_SMEM>>>(x, nullptr, nullptr, XcA, nullptr, part, 0);
    stats2_k<<<Bb, 256>>>(part, gn1_w, gn1_b, scl, shf);
    aprep_k<<<agrid, 256>>>(w1, b1, scl, shf, Abuf, bias2);
    gemm_k<0,0,0><<<ggrid, 256, GEMM_SMEM>>>(Abuf, XcA, bias2, bufAh,
                                             nullptr, nullptr, nullptr, nullptr);
    dw3x3_k<<<dgrid, 256>>>(bufAh, w2, b2, bufBh);
    prep_k<__half><<<pgrid, 256, PREP_SMEM>>>(bufBh, wg1, bg1, XcB, ppart, nullptr, 1);
    att_k<<<Bb, 256>>>(ppart, w_sca, b_sca, attv);
    aprep_k<<<agrid, 256>>>(w3, b3, attv, nullptr, Abuf, bias2);
    // x1 = y*beta + x -> bufX1 (fp32) ; + XcA (fp16 transposed) ; + GN2 partials
    gemm_k<1,1,1><<<ggrid, 256, GEMM_SMEM>>>(Abuf, XcB, bias2, bufX1,
                                             beta, x, part2, XcA);

    // ---- path 2 ----
    stats2_k<<<Bb, 256>>>(part2, gn2_w, gn2_b, scl, shf);
    aprep_k<<<agrid, 256>>>(w4, b4, scl, shf, Abuf, bias2);
    gemm_k<0,0,0><<<ggrid, 256, GEMM_SMEM>>>(Abuf, XcA, bias2, bufAh,
                                             nullptr, nullptr, nullptr, nullptr);
    prep_k<__half><<<pgrid, 256, PREP_SMEM>>>(bufAh, wg2, bg2, XcB, nullptr, nullptr, 1);
    aprep_k<<<agrid, 256>>>(w5, b5, nullptr, nullptr, Abuf, bias2);
    gemm_k<1,0,0><<<ggrid, 256, GEMM_SMEM>>>(Abuf, XcB, bias2, out,
                                             gamma, bufX1, nullptr, nullptr);
}

// round 14
// speedup vs baseline: 1.2417x; 1.1983x over previous
#include <cuda_runtime.h>
#include <cuda_fp16.h>
#include <math.h>
#include <stdint.h>

#define Cc   256
#define Hh   128
#define Wwid 128
#define HW   16384
#define CHW  4194304
#define Bb   8

// ---------------- static scratch ----------------
__device__ __align__(1024) __half g_bufAh[(size_t)Bb * CHW];   // conv1/conv4 out (fp16)
__device__ __align__(1024) __half g_bufBh[(size_t)Bb * CHW];   // dw3x3 out (fp16)
__device__ __align__(1024) __half g_XcA[(size_t)Bb * HW * 256]; // x / x1 transposed fp16
__device__ __align__(1024) __half g_XcB[(size_t)Bb * HW * 256];
__device__ __align__(1024) __half g_Abuf[(size_t)Bb * 256 * 256]; // A fp16
__device__ float  g_bias2[Bb * Cc];
__device__ double g_part[Bb * 256 * 2];      // GN1 partials (from prep1)
__device__ double g_part2[Bb * 256 * 2];     // GN2 partials (from gemm3 epilogue)
__device__ float  g_ppart[(size_t)Bb * Cc * 256];
__device__ float  g_scale[Bb * Cc];
__device__ float  g_shift[Bb * Cc];
__device__ float  g_att[Bb * Cc];

__device__ __forceinline__ float gelu1(float x) {
    return 0.5f * x * (1.0f + erff(x * 0.70710678118654752440f));
}

// ---------------- PTX helpers ----------------
__device__ __forceinline__ uint32_t smem_u32(const void* p) {
    uint32_t a;
    asm("{ .reg .u64 t; cvta.to.shared.u64 t, %1; cvt.u32.u64 %0, t; }" : "=r"(a) : "l"(p));
    return a;
}
#define SWZ128(off) ((off) ^ (((off) >> 3) & 0x70))
#define CP_ASYNC16(sa, g) asm volatile("cp.async.cg.shared.global [%0], [%1], 16;" :: "r"(sa), "l"(g) : "memory")
#define CP_COMMIT() asm volatile("cp.async.commit_group;" ::: "memory")
#define CP_WAIT1()  asm volatile("cp.async.wait_group 1;" ::: "memory")
#define CP_WAIT0()  asm volatile("cp.async.wait_group 0;" ::: "memory")

__device__ __forceinline__ void ldsm4(uint32_t& r0, uint32_t& r1, uint32_t& r2, uint32_t& r3,
                                      uint32_t a) {
    asm volatile("ldmatrix.sync.aligned.m8n8.x4.shared.b16 {%0,%1,%2,%3}, [%4];"
                 : "=r"(r0), "=r"(r1), "=r"(r2), "=r"(r3) : "r"(a));
}
__device__ __forceinline__ void mma16816(float* c, uint32_t a0, uint32_t a1, uint32_t a2,
                                         uint32_t a3, uint32_t b0, uint32_t b1) {
    asm volatile("mma.sync.aligned.m16n8k16.row.col.f32.f16.f16.f32 "
                 "{%0,%1,%2,%3}, {%4,%5,%6,%7}, {%8,%9}, {%0,%1,%2,%3};"
                 : "+f"(c[0]), "+f"(c[1]), "+f"(c[2]), "+f"(c[3])
                 : "r"(a0), "r"(a1), "r"(a2), "r"(a3), "r"(b0), "r"(b1));
}

// ---------------- stats reduce ----------------
__global__ void __launch_bounds__(256) stats2_k(const double* __restrict__ part,
                                                const float* __restrict__ gw,
                                                const float* __restrict__ gb,
                                                float* __restrict__ scale,
                                                float* __restrict__ shift) {
    int b = blockIdx.x, t = threadIdx.x;
    __shared__ double ss[256], ss2[256];
    __shared__ float smean, srstd;
    ss[t]  = part[(b * 256 + t) * 2 + 0];
    ss2[t] = part[(b * 256 + t) * 2 + 1];
    __syncthreads();
    for (int off = 128; off > 0; off >>= 1) {
        if (t < off) { ss[t] += ss[t + off]; ss2[t] += ss2[t + off]; }
        __syncthreads();
    }
    if (t == 0) {
        double m = ss[0] / (double)CHW;
        double v = ss2[0] / (double)CHW - m * m;
        smean = (float)m;
        srstd = rsqrtf((float)v + 1e-5f);
    }
    __syncthreads();
    float sc = srstd * gw[t];
    scale[b * Cc + t] = sc;
    shift[b * Cc + t] = gb[t] - smean * sc;
}

// ---------------- prep: (optional gelu^2 + grouped) -> transpose -> fp16
template <typename T>
__global__ void __launch_bounds__(256) prep_k(const T* __restrict__ in,
                                              const float* __restrict__ wg,
                                              const float* __restrict__ bg,
                                              __half* __restrict__ out,
                                              float* __restrict__ ppart,
                                              double* __restrict__ part,
                                              int do_gelu) {
    extern __shared__ __align__(16) char sm[];
    char* ot = sm;                              // 64 px rows x 516 bytes = 33024
    float* sacc = (float*)(sm + 33024);         // 512 floats
    float* sf   = (float*)(sm + 35072);         // 512 floats (stats)
    int t = threadIdx.x;
    int b = blockIdx.y, pt = blockIdx.x;
    int p0 = pt * 64;
    int gq = t >> 6, pp = t & 63;
    size_t ibase = (size_t)b * CHW + p0 + pp;

    float fs = 0.f, fs2 = 0.f;
#pragma unroll 4
    for (int gi = 0; gi < 16; gi++) {
        int g = gq * 16 + gi;
        int c0 = g * 4;
        float v[4];
#pragma unroll
        for (int i = 0; i < 4; i++) {
            float x = (float)in[ibase + (size_t)(c0 + i) * HW];
            if (part) { fs += x; fs2 += x * x; }
            v[i] = do_gelu ? gelu1(gelu1(x)) : x;
        }
        float u[4];
        if (wg) {
#pragma unroll
            for (int o = 0; o < 4; o++) {
                float s = __ldg(&bg[c0 + o]);
#pragma unroll
                for (int i = 0; i < 4; i++) s += __ldg(&wg[g * 16 + o * 4 + i]) * v[i];
                u[o] = s;
            }
        } else {
#pragma unroll
            for (int o = 0; o < 4; o++) u[o] = v[o];
        }
#pragma unroll
        for (int o = 0; o < 4; o++) {
            int c = c0 + o;
            *(__half*)(ot + pp * 516 + c * 2) = __float2half(u[o]);
            if (ppart) {
                float s = u[o];
#pragma unroll
                for (int off = 16; off > 0; off >>= 1)
                    s += __shfl_down_sync(0xffffffffu, s, off);
                if ((t & 31) == 0) sacc[c * 2 + ((t >> 5) & 1)] = s;
            }
        }
    }
    __syncthreads();
    uint32_t* og = (uint32_t*)out;
#pragma unroll
    for (int it = 0; it < 32; it++) {
        int idx = it * 256 + t;
        int r = idx >> 7, ww = idx & 127;
        og[((size_t)b * HW + p0 + r) * 128 + ww] = *(uint32_t*)(ot + r * 516 + ww * 4);
    }
    if (ppart) {
        float s2 = sacc[t * 2] + sacc[t * 2 + 1];
        ppart[((size_t)b * Cc + t) * 256 + pt] = s2;
    }
    if (part) {
        sf[t] = fs; sf[256 + t] = fs2;
        __syncthreads();
        for (int off = 128; off > 0; off >>= 1) {
            if (t < off) { sf[t] += sf[t + off]; sf[256 + t] += sf[256 + t + off]; }
            __syncthreads();
        }
        if (t == 0) {
            part[((size_t)b * 256 + pt) * 2 + 0] = (double)sf[0];
            part[((size_t)b * 256 + pt) * 2 + 1] = (double)sf[256];
        }
    }
}

// ---------------- A prep ----------------
__global__ void __launch_bounds__(256) aprep_k(const float* __restrict__ W,
                                               const float* __restrict__ bias,
                                               const float* __restrict__ sc,
                                               const float* __restrict__ sh,
                                               __half* __restrict__ A,
                                               float* __restrict__ bias2) {
    int o = blockIdx.x, b = blockIdx.y, t = threadIdx.x;
    float w = __ldg(&W[o * 256 + t]);
    float s = sc ? w * sc[b * Cc + t] : w;
    A[((size_t)b * 256 + o) * 256 + t] = __float2half(s);

    __shared__ float red[256];
    red[t] = sh ? w * sh[b * Cc + t] : 0.f;
    __syncthreads();
    for (int off = 128; off > 0; off >>= 1) {
        if (t < off) red[t] += red[t + off];
        __syncthreads();
    }
    if (t == 0) bias2[b * Cc + o] = __ldg(&bias[o]) + red[0];
}

// ---------------- fp16 GEMM via mma.sync (K=256, 4 chunks) ----------------
// EPI 0: out fp16 CHW.
// EPI 1: z = y*echan + resT (fp16 [p][c] slab via smem stage);
//        O32: z -> fp32 CHW out; STAT: GN partials; XCOUT: z -> fp16 [p][c] slab.
__device__ __forceinline__ void load_chunk(int i, int t, uint32_t sb,
                                           const __half* Ab, const __half* Bbp) {
    int col = i * 64;
    uint32_t abase = sb + (i % 3) * 32768;
    uint32_t bbase = abase + 16384;
    int row = t >> 3, k8 = t & 7;
#pragma unroll
    for (int j = 0; j < 4; j++) {
        int r = row + j * 32;
        CP_ASYNC16(abase + SWZ128(r * 128 + k8 * 16), Ab + (size_t)r * 256 + col + k8 * 8);
        CP_ASYNC16(bbase + SWZ128(r * 128 + k8 * 16), Bbp + (size_t)r * 256 + col + k8 * 8);
    }
}

template <int EPI, int STAT, int XCOUT, int O32>
__global__ void __launch_bounds__(256, 2) gemm_k(
    const __half* __restrict__ A, const __half* __restrict__ Xc,
    const float* __restrict__ bias2, float* __restrict__ out32,
    __half* __restrict__ out16,
    const float* __restrict__ echan, const __half* __restrict__ resT,
    double* __restrict__ statp, __half* __restrict__ xcout) {

    extern __shared__ __align__(1024) char sm[];
    uint32_t sb = smem_u32(sm);
    int t = threadIdx.x, lane = t & 31, w = t >> 5;
    int wm = w >> 2, wn = w & 3;
    int o0 = blockIdx.x * 128, p0 = blockIdx.y * 128, b = blockIdx.z;
    const __half* Ab  = A  + ((size_t)b * 256 + o0) * 256;
    const __half* Bbp = Xc + ((size_t)b * HW  + p0) * 256;

    load_chunk(0, t, sb, Ab, Bbp); CP_COMMIT();
    load_chunk(1, t, sb, Ab, Bbp); CP_COMMIT();

    float acc[4][4][4];
#pragma unroll
    for (int mi = 0; mi < 4; mi++)
#pragma unroll
        for (int ni = 0; ni < 4; ni++)
#pragma unroll
            for (int q = 0; q < 4; q++) acc[mi][ni][q] = 0.f;

#pragma unroll
    for (int i = 0; i < 4; i++) {
        if (i == 3) { CP_WAIT0(); } else { CP_WAIT1(); }
        __syncthreads();
        if (i + 2 < 4) { load_chunk(i + 2, t, sb, Ab, Bbp); CP_COMMIT(); }

        uint32_t as = sb + (i % 3) * 32768, bs = as + 16384;
#pragma unroll
        for (int k2 = 0; k2 < 4; k2++) {
            uint32_t a[4][4];
#pragma unroll
            for (int mi = 0; mi < 4; mi++) {
                int r  = wm * 64 + mi * 16 + (lane & 15);
                int ch = k2 * 2 + (lane >> 4);
                ldsm4(a[mi][0], a[mi][1], a[mi][2], a[mi][3],
                      as + r * 128 + ((ch ^ (r & 7)) * 16));
            }
            uint32_t bb[2][4];
#pragma unroll
            for (int h = 0; h < 2; h++) {
                int r  = wn * 32 + h * 16 + ((lane >> 4) & 1) * 8 + (lane & 7);
                int ch = k2 * 2 + ((lane >> 3) & 1);
                ldsm4(bb[h][0], bb[h][1], bb[h][2], bb[h][3],
                      bs + r * 128 + ((ch ^ (r & 7)) * 16));
            }
#pragma unroll
            for (int mi = 0; mi < 4; mi++)
#pragma unroll
                for (int ni = 0; ni < 4; ni++) {
                    int h = ni >> 1, q = (ni & 1) * 2;
                    mma16816(acc[mi][ni], a[mi][0], a[mi][1], a[mi][2], a[mi][3],
                             bb[h][q], bb[h][q + 1]);
                }
        }
        __syncthreads();
    }

    int g = lane >> 2, i4 = lane & 3;
    char*  rsm  = sm;                    // residual staging [128 p][272 B] = 34816
    char*  st16 = sm + 36864;            // XCOUT staging [128 p][260 B] = 33280
    float* sf   = (float*)(sm + 73728);  // STAT staging: 512 floats

    if (EPI) {
        // stage residual tile: XcA rows p0..p0+127, cols o0..o0+127 (256B each)
        const __half* rsl = resT + ((size_t)b * HW + p0) * 256 + o0;
#pragma unroll
        for (int j = 0; j < 8; j++) {
            int idx = j * 256 + t;
            int r = idx >> 4, ck = idx & 15;
            CP_ASYNC16(sb + r * 272 + ck * 16, rsl + (size_t)r * 256 + ck * 8);
        }
        CP_COMMIT(); CP_WAIT0();
        __syncthreads();
    }

    float ls = 0.f, ls2 = 0.f;
#pragma unroll
    for (int mi = 0; mi < 4; mi++) {
        int o = o0 + wm * 64 + mi * 16 + g;
        int ol = wm * 64 + mi * 16 + g;
        float bv0 = bias2[b * Cc + o], bv1 = bias2[b * Cc + o + 8];
        float e0 = 1.f, e1 = 1.f;
        if (EPI) { e0 = __ldg(&echan[o]); e1 = __ldg(&echan[o + 8]); }
        size_t r0b = (size_t)b * CHW + (size_t)o * HW;
        size_t r1b = r0b + (size_t)8 * HW;
#pragma unroll
        for (int ni = 0; ni < 4; ni++) {
            int pl = wn * 32 + ni * 8 + i4 * 2;
            int p = p0 + pl;
            float y00 = acc[mi][ni][0] + bv0, y01 = acc[mi][ni][1] + bv0;
            float y10 = acc[mi][ni][2] + bv1, y11 = acc[mi][ni][3] + bv1;
            if (EPI) {
                float q00 = __half2float(*(__half*)(rsm + (pl)     * 272 + ol * 2));
                float q01 = __half2float(*(__half*)(rsm + (pl + 1) * 272 + ol * 2));
                float q10 = __half2float(*(__half*)(rsm + (pl)     * 272 + (ol + 8) * 2));
                float q11 = __half2float(*(__half*)(rsm + (pl + 1) * 272 + (ol + 8) * 2));
                float z00 = y00 * e0 + q00, z01 = y01 * e0 + q01;
                float z10 = y10 * e1 + q10, z11 = y11 * e1 + q11;
                if (O32) {
                    float2 z0, z1;
                    z0.x = z00; z0.y = z01; z1.x = z10; z1.y = z11;
                    __stcs((float2*)(out32 + r0b + p), z0);
                    __stcs((float2*)(out32 + r1b + p), z1);
                }
                if (STAT) {
                    ls  += z00 + z01 + z10 + z11;
                    ls2 += z00 * z00 + z01 * z01 + z10 * z10 + z11 * z11;
                }
                if (XCOUT) {
                    *(__half*)(st16 + (pl)     * 260 + ol * 2)       = __float2half(z00);
                    *(__half*)(st16 + (pl + 1) * 260 + ol * 2)       = __float2half(z01);
                    *(__half*)(st16 + (pl)     * 260 + (ol + 8) * 2) = __float2half(z10);
                    *(__half*)(st16 + (pl + 1) * 260 + (ol + 8) * 2) = __float2half(z11);
                }
            } else {
                __half2 h0, h1;
                h0.x = __float2half(y00); h0.y = __float2half(y01);
                h1.x = __float2half(y10); h1.y = __float2half(y11);
                *(__half2*)(out16 + r0b + p) = h0;
                *(__half2*)(out16 + r1b + p) = h1;
            }
        }
    }

    if (XCOUT) {
        __syncthreads();
        uint32_t* og = (uint32_t*)xcout;
#pragma unroll
        for (int it = 0; it < 32; it++) {
            int idx = it * 256 + t;
            int r = idx >> 6, ww = idx & 63;
            og[((size_t)b * HW + p0 + r) * 128 + (o0 >> 1) + ww] =
                *(uint32_t*)(st16 + r * 260 + ww * 4);
        }
    }

    if (STAT) {
        sf[t] = ls; sf[256 + t] = ls2;
        __syncthreads();
        for (int off = 128; off > 0; off >>= 1) {
            if (t < off) { sf[t] += sf[t + off]; sf[256 + t] += sf[256 + t + off]; }
            __syncthreads();
        }
        if (t == 0) {
            int idx = blockIdx.x + 2 * blockIdx.y;
            statp[((size_t)b * 256 + idx) * 2 + 0] = (double)sf[0];
            statp[((size_t)b * 256 + idx) * 2 + 1] = (double)sf[256];
        }
    }
}

// ---------------- depthwise 3x3: padded smem + 4px/thread vectorized ----------
__global__ void __launch_bounds__(256) dw3x3_k(const __half* __restrict__ in,
                                               const float* __restrict__ w2,
                                               const float* __restrict__ b2,
                                               __half* __restrict__ out) {
    __shared__ float s[34][132];
    int t = threadIdx.x;
    int b = blockIdx.z, c = blockIdx.y;
    int r0 = blockIdx.x * 32;
    size_t base = (size_t)b * CHW + (size_t)c * HW;

    if (t < 34) { s[t][0] = 0.f; s[t][129] = 0.f; s[t][130] = 0.f; s[t][131] = 0.f; }
#pragma unroll
    for (int it = 0; it < 17; it++) {
        int idx = it * 256 + t;
        int rr = idx >> 7, cc = idx & 127;
        int gr = r0 - 1 + rr;
        s[rr][cc + 1] = (gr >= 0 && gr < Hh) ? __half2float(in[base + (size_t)gr * Wwid + cc]) : 0.f;
    }
    float wv[9];
#pragma unroll
    for (int i = 0; i < 9; i++) wv[i] = __ldg(&w2[c * 9 + i]);
    float bias = __ldg(&b2[c]);
    __syncthreads();

    int tc = (t & 31) * 4;
    int tr = t >> 5;
#pragma unroll
    for (int rb = 0; rb < 4; rb++) {
        int r = rb * 8 + tr;
        int sr = r + 1;
        float a0 = bias, a1 = bias, a2 = bias, a3 = bias;
#pragma unroll
        for (int dy = 0; dy < 3; dy++) {
            const float* row = &s[sr - 1 + dy][tc];
            float4 va = *(const float4*)(row);
            float2 vb = *(const float2*)(row + 4);
            float w0 = wv[dy * 3 + 0], w1 = wv[dy * 3 + 1], w2v = wv[dy * 3 + 2];
            a0 += w0 * va.x + w1 * va.y + w2v * va.z;
            a1 += w0 * va.y + w1 * va.z + w2v * va.w;
            a2 += w0 * va.z + w1 * va.w + w2v * vb.x;
            a3 += w0 * va.w + w1 * vb.x + w2v * vb.y;
        }
        __half2 h0, h1;
        h0.x = __float2half(a0); h0.y = __float2half(a1);
        h1.x = __float2half(a2); h1.y = __float2half(a3);
        __half2* op = (__half2*)(out + base + (size_t)(r0 + r) * Wwid + tc);
        op[0] = h0; op[1] = h1;
    }
}

// ---------------- channel attention ----------------
__global__ void __launch_bounds__(256) att_k(const float* __restrict__ ppart,
                                             const float* __restrict__ wsca,
                                             const float* __restrict__ bsca,
                                             float* __restrict__ att) {
    __shared__ float sp[256];
    int b = blockIdx.x, t = threadIdx.x;
    float s = 0.f;
    const float* pr = ppart + ((size_t)b * Cc + t) * 256;
#pragma unroll 8
    for (int j = 0; j < 256; j++) s += pr[j];
    sp[t] = s * (1.f / (float)HW);
    __syncthreads();
    float acc = __ldg(&bsca[t]);
    const float* wrow = wsca + (size_t)t * 256;
#pragma unroll 8
    for (int c = 0; c < 256; c++) acc += sp[c] * __ldg(&wrow[c]);
    att[b * Cc + t] = acc;
}

// ---------------- launch ----------------
extern "C" void kernel_launch(void* const* d_in, const int* in_sizes, int n_in,
                              void* d_out, int out_size) {
    const float* x     = (const float*)d_in[0];
    const float* gn1_w = (const float*)d_in[1];
    const float* gn1_b = (const float*)d_in[2];
    const float* w1    = (const float*)d_in[3];
    const float* b1    = (const float*)d_in[4];
    const float* w2    = (const float*)d_in[5];
    const float* b2    = (const float*)d_in[6];
    const float* wg1   = (const float*)d_in[7];
    const float* bg1   = (const float*)d_in[8];
    const float* w_sca = (const float*)d_in[9];
    const float* b_sca = (const float*)d_in[10];
    const float* w3    = (const float*)d_in[11];
    const float* b3    = (const float*)d_in[12];
    const float* gn2_w = (const float*)d_in[13];
    const float* gn2_b = (const float*)d_in[14];
    const float* w4    = (const float*)d_in[15];
    const float* b4    = (const float*)d_in[16];
    const float* wg2   = (const float*)d_in[17];
    const float* bg2   = (const float*)d_in[18];
    const float* w5    = (const float*)d_in[19];
    const float* b5    = (const float*)d_in[20];
    const float* beta  = (const float*)d_in[21];
    const float* gamma = (const float*)d_in[22];
    float* out = (float*)d_out;

    float *ppart, *scl, *shf, *attv, *bias2;
    __half *bufAh, *bufBh, *XcA, *XcB, *Abuf;
    double *part, *part2;
    cudaGetSymbolAddress((void**)&bufAh, g_bufAh);
    cudaGetSymbolAddress((void**)&bufBh, g_bufBh);
    cudaGetSymbolAddress((void**)&XcA,   g_XcA);
    cudaGetSymbolAddress((void**)&XcB,   g_XcB);
    cudaGetSymbolAddress((void**)&Abuf,  g_Abuf);
    cudaGetSymbolAddress((void**)&bias2, g_bias2);
    cudaGetSymbolAddress((void**)&part,  g_part);
    cudaGetSymbolAddress((void**)&part2, g_part2);
    cudaGetSymbolAddress((void**)&ppart, g_ppart);
    cudaGetSymbolAddress((void**)&scl,   g_scale);
    cudaGetSymbolAddress((void**)&shf,   g_shift);
    cudaGetSymbolAddress((void**)&attv,  g_att);

    const int GEMM_SMEM = 3 * 32768;
    const int PREP_SMEM = 33024 + 2048 + 2048;
    cudaFuncSetAttribute(gemm_k<0,0,0,0>, cudaFuncAttributeMaxDynamicSharedMemorySize, GEMM_SMEM);
    cudaFuncSetAttribute(gemm_k<1,1,1,0>, cudaFuncAttributeMaxDynamicSharedMemorySize, GEMM_SMEM);
    cudaFuncSetAttribute(gemm_k<1,0,0,1>, cudaFuncAttributeMaxDynamicSharedMemorySize, GEMM_SMEM);
    cudaFuncSetAttribute(prep_k<float>,  cudaFuncAttributeMaxDynamicSharedMemorySize, PREP_SMEM);
    cudaFuncSetAttribute(prep_k<__half>, cudaFuncAttributeMaxDynamicSharedMemorySize, PREP_SMEM);

    dim3 ggrid(2, 128, Bb);
    dim3 pgrid(256, Bb);
    dim3 agrid(256, Bb);
    dim3 dgrid(4, Cc, Bb);

    // ---- path 1 ----
    prep_k<float><<<pgrid, 256, PREP_SMEM>>>(x, nullptr, nullptr, XcA, nullptr, part, 0);
    stats2_k<<<Bb, 256>>>(part, gn1_w, gn1_b, scl, shf);
    aprep_k<<<agrid, 256>>>(w1, b1, scl, shf, Abuf, bias2);
    gemm_k<0,0,0,0><<<ggrid, 256, GEMM_SMEM>>>(Abuf, XcA, bias2, nullptr, bufAh,
                                               nullptr, nullptr, nullptr, nullptr);
    dw3x3_k<<<dgrid, 256>>>(bufAh, w2, b2, bufBh);
    prep_k<__half><<<pgrid, 256, PREP_SMEM>>>(bufBh, wg1, bg1, XcB, ppart, nullptr, 1);
    att_k<<<Bb, 256>>>(ppart, w_sca, b_sca, attv);
    aprep_k<<<agrid, 256>>>(w3, b3, attv, nullptr, Abuf, bias2);
    // x1 = y*beta + x(fp16 from XcA) -> XcA (fp16 transposed) + GN2 partials
    gemm_k<1,1,1,0><<<ggrid, 256, GEMM_SMEM>>>(Abuf, XcB, bias2, nullptr, nullptr,
                                               beta, XcA, part2, XcA);

    // ---- path 2 ----
    stats2_k<<<Bb, 256>>>(part2, gn2_w, gn2_b, scl, shf);
    aprep_k<<<agrid, 256>>>(w4, b4, scl, shf, Abuf, bias2);
    gemm_k<0,0,0,0><<<ggrid, 256, GEMM_SMEM>>>(Abuf, XcA, bias2, nullptr, bufAh,
                                               nullptr, nullptr, nullptr, nullptr);
    prep_k<__half><<<pgrid, 256, PREP_SMEM>>>(bufAh, wg2, bg2, XcB, nullptr, nullptr, 1);
    aprep_k<<<agrid, 256>>>(w5, b5, nullptr, nullptr, Abuf, bias2);
    // out = y*gamma + x1(fp16 from XcA) -> fp32 out
    gemm_k<1,0,0,1><<<ggrid, 256, GEMM_SMEM>>>(Abuf, XcB, bias2, out, nullptr,
                                               gamma, XcA, nullptr, nullptr);
}

// round 15
// speedup vs baseline: 1.2818x; 1.0324x over previous
#include <cuda_runtime.h>
#include <cuda_fp16.h>
#include <math.h>
#include <stdint.h>

#define Cc   256
#define Hh   128
#define Wwid 128
#define HW   16384
#define CHW  4194304
#define Bb   8

// ---------------- static scratch ----------------
__device__ __align__(1024) __half g_bufAh[(size_t)Bb * CHW];   // conv1 out (fp16)
__device__ __align__(1024) __half g_bufBh[(size_t)Bb * CHW];   // dw3x3 out (fp16)
__device__ __align__(1024) __half g_XcA[(size_t)Bb * HW * 256]; // x / x1 transposed fp16
__device__ __align__(1024) __half g_XcB[(size_t)Bb * HW * 256];
__device__ __align__(1024) __half g_Abuf[(size_t)Bb * 256 * 256]; // A fp16
__device__ float  g_bias2[Bb * Cc];
__device__ double g_part[Bb * 256 * 2];      // GN1 partials (from prep1)
__device__ double g_part2[Bb * 256 * 2];     // GN2 partials (from gemm3 epilogue)
__device__ float  g_ppart[(size_t)Bb * Cc * 256];
__device__ float  g_scale[Bb * Cc];
__device__ float  g_shift[Bb * Cc];
__device__ float  g_att[Bb * Cc];

__device__ __forceinline__ float gelu1(float x) {
    return 0.5f * x * (1.0f + erff(x * 0.70710678118654752440f));
}

// ---------------- PTX helpers ----------------
__device__ __forceinline__ uint32_t smem_u32(const void* p) {
    uint32_t a;
    asm("{ .reg .u64 t; cvta.to.shared.u64 t, %1; cvt.u32.u64 %0, t; }" : "=r"(a) : "l"(p));
    return a;
}
#define SWZ128(off) ((off) ^ (((off) >> 3) & 0x70))
#define CP_ASYNC16(sa, g) asm volatile("cp.async.cg.shared.global [%0], [%1], 16;" :: "r"(sa), "l"(g) : "memory")
#define CP_COMMIT() asm volatile("cp.async.commit_group;" ::: "memory")
#define CP_WAIT1()  asm volatile("cp.async.wait_group 1;" ::: "memory")
#define CP_WAIT0()  asm volatile("cp.async.wait_group 0;" ::: "memory")

__device__ __forceinline__ void ldsm4(uint32_t& r0, uint32_t& r1, uint32_t& r2, uint32_t& r3,
                                      uint32_t a) {
    asm volatile("ldmatrix.sync.aligned.m8n8.x4.shared.b16 {%0,%1,%2,%3}, [%4];"
                 : "=r"(r0), "=r"(r1), "=r"(r2), "=r"(r3) : "r"(a));
}
__device__ __forceinline__ void mma16816(float* c, uint32_t a0, uint32_t a1, uint32_t a2,
                                         uint32_t a3, uint32_t b0, uint32_t b1) {
    asm volatile("mma.sync.aligned.m16n8k16.row.col.f32.f16.f16.f32 "
                 "{%0,%1,%2,%3}, {%4,%5,%6,%7}, {%8,%9}, {%0,%1,%2,%3};"
                 : "+f"(c[0]), "+f"(c[1]), "+f"(c[2]), "+f"(c[3])
                 : "r"(a0), "r"(a1), "r"(a2), "r"(a3), "r"(b0), "r"(b1));
}

// ---------------- stats reduce ----------------
__global__ void __launch_bounds__(256) stats2_k(const double* __restrict__ part,
                                                const float* __restrict__ gw,
                                                const float* __restrict__ gb,
                                                float* __restrict__ scale,
                                                float* __restrict__ shift) {
    int b = blockIdx.x, t = threadIdx.x;
    __shared__ double ss[256], ss2[256];
    __shared__ float smean, srstd;
    ss[t]  = part[(b * 256 + t) * 2 + 0];
    ss2[t] = part[(b * 256 + t) * 2 + 1];
    __syncthreads();
    for (int off = 128; off > 0; off >>= 1) {
        if (t < off) { ss[t] += ss[t + off]; ss2[t] += ss2[t + off]; }
        __syncthreads();
    }
    if (t == 0) {
        double m = ss[0] / (double)CHW;
        double v = ss2[0] / (double)CHW - m * m;
        smean = (float)m;
        srstd = rsqrtf((float)v + 1e-5f);
    }
    __syncthreads();
    float sc = srstd * gw[t];
    scale[b * Cc + t] = sc;
    shift[b * Cc + t] = gb[t] - smean * sc;
}

// ---------------- prep: (optional gelu^2 + grouped) -> transpose -> fp16
template <typename T>
__global__ void __launch_bounds__(256) prep_k(const T* __restrict__ in,
                                              const float* __restrict__ wg,
                                              const float* __restrict__ bg,
                                              __half* __restrict__ out,
                                              float* __restrict__ ppart,
                                              double* __restrict__ part,
                                              int do_gelu) {
    extern __shared__ __align__(16) char sm[];
    char* ot = sm;                              // 64 px rows x 516 bytes = 33024
    float* sacc = (float*)(sm + 33024);         // 512 floats
    float* sf   = (float*)(sm + 35072);         // 512 floats (stats)
    int t = threadIdx.x;
    int b = blockIdx.y, pt = blockIdx.x;
    int p0 = pt * 64;
    int gq = t >> 6, pp = t & 63;
    size_t ibase = (size_t)b * CHW + p0 + pp;

    float fs = 0.f, fs2 = 0.f;
#pragma unroll 4
    for (int gi = 0; gi < 16; gi++) {
        int g = gq * 16 + gi;
        int c0 = g * 4;
        float v[4];
#pragma unroll
        for (int i = 0; i < 4; i++) {
            float x = (float)in[ibase + (size_t)(c0 + i) * HW];
            if (part) { fs += x; fs2 += x * x; }
            v[i] = do_gelu ? gelu1(gelu1(x)) : x;
        }
        float u[4];
        if (wg) {
#pragma unroll
            for (int o = 0; o < 4; o++) {
                float s = __ldg(&bg[c0 + o]);
#pragma unroll
                for (int i = 0; i < 4; i++) s += __ldg(&wg[g * 16 + o * 4 + i]) * v[i];
                u[o] = s;
            }
        } else {
#pragma unroll
            for (int o = 0; o < 4; o++) u[o] = v[o];
        }
#pragma unroll
        for (int o = 0; o < 4; o++) {
            int c = c0 + o;
            *(__half*)(ot + pp * 516 + c * 2) = __float2half(u[o]);
            if (ppart) {
                float s = u[o];
#pragma unroll
                for (int off = 16; off > 0; off >>= 1)
                    s += __shfl_down_sync(0xffffffffu, s, off);
                if ((t & 31) == 0) sacc[c * 2 + ((t >> 5) & 1)] = s;
            }
        }
    }
    __syncthreads();
    uint32_t* og = (uint32_t*)out;
#pragma unroll
    for (int it = 0; it < 32; it++) {
        int idx = it * 256 + t;
        int r = idx >> 7, ww = idx & 127;
        og[((size_t)b * HW + p0 + r) * 128 + ww] = *(uint32_t*)(ot + r * 516 + ww * 4);
    }
    if (ppart) {
        float s2 = sacc[t * 2] + sacc[t * 2 + 1];
        ppart[((size_t)b * Cc + t) * 256 + pt] = s2;
    }
    if (part) {
        sf[t] = fs; sf[256 + t] = fs2;
        __syncthreads();
        for (int off = 128; off > 0; off >>= 1) {
            if (t < off) { sf[t] += sf[t + off]; sf[256 + t] += sf[256 + t + off]; }
            __syncthreads();
        }
        if (t == 0) {
            part[((size_t)b * 256 + pt) * 2 + 0] = (double)sf[0];
            part[((size_t)b * 256 + pt) * 2 + 1] = (double)sf[256];
        }
    }
}

// ---------------- A prep ----------------
__global__ void __launch_bounds__(256) aprep_k(const float* __restrict__ W,
                                               const float* __restrict__ bias,
                                               const float* __restrict__ sc,
                                               const float* __restrict__ sh,
                                               __half* __restrict__ A,
                                               float* __restrict__ bias2) {
    int o = blockIdx.x, b = blockIdx.y, t = threadIdx.x;
    float w = __ldg(&W[o * 256 + t]);
    float s = sc ? w * sc[b * Cc + t] : w;
    A[((size_t)b * 256 + o) * 256 + t] = __float2half(s);

    __shared__ float red[256];
    red[t] = sh ? w * sh[b * Cc + t] : 0.f;
    __syncthreads();
    for (int off = 128; off > 0; off >>= 1) {
        if (t < off) red[t] += red[t + off];
        __syncthreads();
    }
    if (t == 0) bias2[b * Cc + o] = __ldg(&bias[o]) + red[0];
}

// ---------------- fp16 GEMM via mma.sync (K=256, 4 chunks) ----------------
// EPI 0, GEL 0: out fp16 CHW.
// EPI 0, GEL 1: gelu^2(y) + grouped 1x1 -> transposed fp16 xcout slab.
// EPI 1: z = y*echan + resT (fp16 [p][c] slab via smem stage);
//        O32: z -> fp32 CHW out; STAT: GN partials; XCOUT: z -> fp16 [p][c] slab.
__device__ __forceinline__ void load_chunk(int i, int t, uint32_t sb,
                                           const __half* Ab, const __half* Bbp) {
    int col = i * 64;
    uint32_t abase = sb + (i % 3) * 32768;
    uint32_t bbase = abase + 16384;
    int row = t >> 3, k8 = t & 7;
#pragma unroll
    for (int j = 0; j < 4; j++) {
        int r = row + j * 32;
        CP_ASYNC16(abase + SWZ128(r * 128 + k8 * 16), Ab + (size_t)r * 256 + col + k8 * 8);
        CP_ASYNC16(bbase + SWZ128(r * 128 + k8 * 16), Bbp + (size_t)r * 256 + col + k8 * 8);
    }
}

template <int EPI, int STAT, int XCOUT, int O32, int GEL>
__global__ void __launch_bounds__(256, 2) gemm_k(
    const __half* __restrict__ A, const __half* __restrict__ Xc,
    const float* __restrict__ bias2, float* __restrict__ out32,
    __half* __restrict__ out16,
    const float* __restrict__ echan, const __half* __restrict__ resT,
    double* __restrict__ statp, __half* __restrict__ xcout,
    const float* __restrict__ wg, const float* __restrict__ bg) {

    extern __shared__ __align__(1024) char sm[];
    uint32_t sb = smem_u32(sm);
    int t = threadIdx.x, lane = t & 31, w = t >> 5;
    int wm = w >> 2, wn = w & 3;
    int o0 = blockIdx.x * 128, p0 = blockIdx.y * 128, b = blockIdx.z;
    const __half* Ab  = A  + ((size_t)b * 256 + o0) * 256;
    const __half* Bbp = Xc + ((size_t)b * HW  + p0) * 256;

    load_chunk(0, t, sb, Ab, Bbp); CP_COMMIT();
    load_chunk(1, t, sb, Ab, Bbp); CP_COMMIT();

    float acc[4][4][4];
#pragma unroll
    for (int mi = 0; mi < 4; mi++)
#pragma unroll
        for (int ni = 0; ni < 4; ni++)
#pragma unroll
            for (int q = 0; q < 4; q++) acc[mi][ni][q] = 0.f;

#pragma unroll
    for (int i = 0; i < 4; i++) {
        if (i == 3) { CP_WAIT0(); } else { CP_WAIT1(); }
        __syncthreads();
        if (i + 2 < 4) { load_chunk(i + 2, t, sb, Ab, Bbp); CP_COMMIT(); }

        uint32_t as = sb + (i % 3) * 32768, bs = as + 16384;
#pragma unroll
        for (int k2 = 0; k2 < 4; k2++) {
            uint32_t a[4][4];
#pragma unroll
            for (int mi = 0; mi < 4; mi++) {
                int r  = wm * 64 + mi * 16 + (lane & 15);
                int ch = k2 * 2 + (lane >> 4);
                ldsm4(a[mi][0], a[mi][1], a[mi][2], a[mi][3],
                      as + r * 128 + ((ch ^ (r & 7)) * 16));
            }
            uint32_t bb[2][4];
#pragma unroll
            for (int h = 0; h < 2; h++) {
                int r  = wn * 32 + h * 16 + ((lane >> 4) & 1) * 8 + (lane & 7);
                int ch = k2 * 2 + ((lane >> 3) & 1);
                ldsm4(bb[h][0], bb[h][1], bb[h][2], bb[h][3],
                      bs + r * 128 + ((ch ^ (r & 7)) * 16));
            }
#pragma unroll
            for (int mi = 0; mi < 4; mi++)
#pragma unroll
                for (int ni = 0; ni < 4; ni++) {
                    int h = ni >> 1, q = (ni & 1) * 2;
                    mma16816(acc[mi][ni], a[mi][0], a[mi][1], a[mi][2], a[mi][3],
                             bb[h][q], bb[h][q + 1]);
                }
        }
        __syncthreads();
    }

    int g = lane >> 2, i4 = lane & 3;
    char*  rsm   = sm;                               // EPI residual staging [128][272]
    char*  st16y = sm;                               // GEL y staging [128 o][260]
    char*  st16  = GEL ? (sm + 33280) : (sm + 36864); // out staging [128 p][260]
    float* sf    = (float*)(sm + 73728);             // STAT: 512 floats

    if (EPI) {
        const __half* rsl = resT + ((size_t)b * HW + p0) * 256 + o0;
#pragma unroll
        for (int j = 0; j < 8; j++) {
            int idx = j * 256 + t;
            int r = idx >> 4, ck = idx & 15;
            CP_ASYNC16(sb + r * 272 + ck * 16, rsl + (size_t)r * 256 + ck * 8);
        }
        CP_COMMIT(); CP_WAIT0();
        __syncthreads();
    }

    float ls = 0.f, ls2 = 0.f;
#pragma unroll
    for (int mi = 0; mi < 4; mi++) {
        int o = o0 + wm * 64 + mi * 16 + g;
        int ol = wm * 64 + mi * 16 + g;
        float bv0 = bias2[b * Cc + o], bv1 = bias2[b * Cc + o + 8];
        float e0 = 1.f, e1 = 1.f;
        if (EPI) { e0 = __ldg(&echan[o]); e1 = __ldg(&echan[o + 8]); }
        size_t r0b = (size_t)b * CHW + (size_t)o * HW;
        size_t r1b = r0b + (size_t)8 * HW;
#pragma unroll
        for (int ni = 0; ni < 4; ni++) {
            int pl = wn * 32 + ni * 8 + i4 * 2;
            int p = p0 + pl;
            float y00 = acc[mi][ni][0] + bv0, y01 = acc[mi][ni][1] + bv0;
            float y10 = acc[mi][ni][2] + bv1, y11 = acc[mi][ni][3] + bv1;
            if (EPI) {
                float q00 = __half2float(*(__half*)(rsm + (pl)     * 272 + ol * 2));
                float q01 = __half2float(*(__half*)(rsm + (pl + 1) * 272 + ol * 2));
                float q10 = __half2float(*(__half*)(rsm + (pl)     * 272 + (ol + 8) * 2));
                float q11 = __half2float(*(__half*)(rsm + (pl + 1) * 272 + (ol + 8) * 2));
                float z00 = y00 * e0 + q00, z01 = y01 * e0 + q01;
                float z10 = y10 * e1 + q10, z11 = y11 * e1 + q11;
                if (O32) {
                    float2 z0, z1;
                    z0.x = z00; z0.y = z01; z1.x = z10; z1.y = z11;
                    __stcs((float2*)(out32 + r0b + p), z0);
                    __stcs((float2*)(out32 + r1b + p), z1);
                }
                if (STAT) {
                    ls  += z00 + z01 + z10 + z11;
                    ls2 += z00 * z00 + z01 * z01 + z10 * z10 + z11 * z11;
                }
                if (XCOUT) {
                    *(__half*)(st16 + (pl)     * 260 + ol * 2)       = __float2half(z00);
                    *(__half*)(st16 + (pl + 1) * 260 + ol * 2)       = __float2half(z01);
                    *(__half*)(st16 + (pl)     * 260 + (ol + 8) * 2) = __float2half(z10);
                    *(__half*)(st16 + (pl + 1) * 260 + (ol + 8) * 2) = __float2half(z11);
                }
            } else if (GEL) {
                __half2 h0, h1;
                h0.x = __float2half(y00); h0.y = __float2half(y01);
                h1.x = __float2half(y10); h1.y = __float2half(y11);
                *(__half2*)(st16y + (ol)     * 260 + pl * 2) = h0;
                *(__half2*)(st16y + (ol + 8) * 260 + pl * 2) = h1;
            } else {
                __half2 h0, h1;
                h0.x = __float2half(y00); h0.y = __float2half(y01);
                h1.x = __float2half(y10); h1.y = __float2half(y11);
                *(__half2*)(out16 + r0b + p) = h0;
                *(__half2*)(out16 + r1b + p) = h1;
            }
        }
    }

    if (GEL) {
        __syncthreads();
        int ph = t & 127, half = t >> 7;
#pragma unroll
        for (int gi = 0; gi < 16; gi++) {
            int gl = half * 16 + gi;
            int cl = gl * 4;
            int gg = (o0 >> 2) + gl;
            float v[4];
#pragma unroll
            for (int i = 0; i < 4; i++) {
                float yv = __half2float(*(__half*)(st16y + (cl + i) * 260 + ph * 2));
                v[i] = gelu1(gelu1(yv));
            }
            float u[4];
#pragma unroll
            for (int o = 0; o < 4; o++) {
                float s = __ldg(&bg[o0 + cl + o]);
#pragma unroll
                for (int i = 0; i < 4; i++) s += __ldg(&wg[gg * 16 + o * 4 + i]) * v[i];
                u[o] = s;
            }
            __half2 h0, h1;
            h0.x = __float2half(u[0]); h0.y = __float2half(u[1]);
            h1.x = __float2half(u[2]); h1.y = __float2half(u[3]);
            *(__half2*)(st16 + ph * 260 + cl * 2)     = h0;
            *(__half2*)(st16 + ph * 260 + cl * 2 + 4) = h1;
        }
    }

    if (XCOUT || GEL) {
        __syncthreads();
        uint32_t* og = (uint32_t*)xcout;
#pragma unroll
        for (int it = 0; it < 32; it++) {
            int idx = it * 256 + t;
            int r = idx >> 6, ww = idx & 63;
            og[((size_t)b * HW + p0 + r) * 128 + (o0 >> 1) + ww] =
                *(uint32_t*)(st16 + r * 260 + ww * 4);
        }
    }

    if (STAT) {
        sf[t] = ls; sf[256 + t] = ls2;
        __syncthreads();
        for (int off = 128; off > 0; off >>= 1) {
            if (t < off) { sf[t] += sf[t + off]; sf[256 + t] += sf[256 + t + off]; }
            __syncthreads();
        }
        if (t == 0) {
            int idx = blockIdx.x + 2 * blockIdx.y;
            statp[((size_t)b * 256 + idx) * 2 + 0] = (double)sf[0];
            statp[((size_t)b * 256 + idx) * 2 + 1] = (double)sf[256];
        }
    }
}

// ---------------- depthwise 3x3: padded smem + 4px/thread vectorized ----------
__global__ void __launch_bounds__(256) dw3x3_k(const __half* __restrict__ in,
                                               const float* __restrict__ w2,
                                               const float* __restrict__ b2,
                                               __half* __restrict__ out) {
    __shared__ float s[34][132];
    int t = threadIdx.x;
    int b = blockIdx.z, c = blockIdx.y;
    int r0 = blockIdx.x * 32;
    size_t base = (size_t)b * CHW + (size_t)c * HW;

    if (t < 34) { s[t][0] = 0.f; s[t][129] = 0.f; s[t][130] = 0.f; s[t][131] = 0.f; }
#pragma unroll
    for (int it = 0; it < 17; it++) {
        int idx = it * 256 + t;
        int rr = idx >> 7, cc = idx & 127;
        int gr = r0 - 1 + rr;
        s[rr][cc + 1] = (gr >= 0 && gr < Hh) ? __half2float(in[base + (size_t)gr * Wwid + cc]) : 0.f;
    }
    float wv[9];
#pragma unroll
    for (int i = 0; i < 9; i++) wv[i] = __ldg(&w2[c * 9 + i]);
    float bias = __ldg(&b2[c]);
    __syncthreads();

    int tc = (t & 31) * 4;
    int tr = t >> 5;
#pragma unroll
    for (int rb = 0; rb < 4; rb++) {
        int r = rb * 8 + tr;
        int sr = r + 1;
        float a0 = bias, a1 = bias, a2 = bias, a3 = bias;
#pragma unroll
        for (int dy = 0; dy < 3; dy++) {
            const float* row = &s[sr - 1 + dy][tc];
            float4 va = *(const float4*)(row);
            float2 vb = *(const float2*)(row + 4);
            float w0 = wv[dy * 3 + 0], w1 = wv[dy * 3 + 1], w2v = wv[dy * 3 + 2];
            a0 += w0 * va.x + w1 * va.y + w2v * va.z;
            a1 += w0 * va.y + w1 * va.z + w2v * va.w;
            a2 += w0 * va.z + w1 * va.w + w2v * vb.x;
            a3 += w0 * va.w + w1 * vb.x + w2v * vb.y;
        }
        __half2 h0, h1;
        h0.x = __float2half(a0); h0.y = __float2half(a1);
        h1.x = __float2half(a2); h1.y = __float2half(a3);
        __half2* op = (__half2*)(out + base + (size_t)(r0 + r) * Wwid + tc);
        op[0] = h0; op[1] = h1;
    }
}

// ---------------- channel attention ----------------
__global__ void __launch_bounds__(256) att_k(const float* __restrict__ ppart,
                                             const float* __restrict__ wsca,
                                             const float* __restrict__ bsca,
                                             float* __restrict__ att) {
    __shared__ float sp[256];
    int b = blockIdx.x, t = threadIdx.x;
    float s = 0.f;
    const float* pr = ppart + ((size_t)b * Cc + t) * 256;
#pragma unroll 8
    for (int j = 0; j < 256; j++) s += pr[j];
    sp[t] = s * (1.f / (float)HW);
    __syncthreads();
    float acc = __ldg(&bsca[t]);
    const float* wrow = wsca + (size_t)t * 256;
#pragma unroll 8
    for (int c = 0; c < 256; c++) acc += sp[c] * __ldg(&wrow[c]);
    att[b * Cc + t] = acc;
}

// ---------------- launch ----------------
extern "C" void kernel_launch(void* const* d_in, const int* in_sizes, int n_in,
                              void* d_out, int out_size) {
    const float* x     = (const float*)d_in[0];
    const float* gn1_w = (const float*)d_in[1];
    const float* gn1_b = (const float*)d_in[2];
    const float* w1    = (const float*)d_in[3];
    const float* b1    = (const float*)d_in[4];
    const float* w2    = (const float*)d_in[5];
    const float* b2    = (const float*)d_in[6];
    const float* wg1   = (const float*)d_in[7];
    const float* bg1   = (const float*)d_in[8];
    const float* w_sca = (const float*)d_in[9];
    const float* b_sca = (const float*)d_in[10];
    const float* w3    = (const float*)d_in[11];
    const float* b3    = (const float*)d_in[12];
    const float* gn2_w = (const float*)d_in[13];
    const float* gn2_b = (const float*)d_in[14];
    const float* w4    = (const float*)d_in[15];
    const float* b4    = (const float*)d_in[16];
    const float* wg2   = (const float*)d_in[17];
    const float* bg2   = (const float*)d_in[18];
    const float* w5    = (const float*)d_in[19];
    const float* b5    = (const float*)d_in[20];
    const float* beta  = (const float*)d_in[21];
    const float* gamma = (const float*)d_in[22];
    float* out = (float*)d_out;

    float *ppart, *scl, *shf, *attv, *bias2;
    __half *bufAh, *bufBh, *XcA, *XcB, *Abuf;
    double *part, *part2;
    cudaGetSymbolAddress((void**)&bufAh, g_bufAh);
    cudaGetSymbolAddress((void**)&bufBh, g_bufBh);
    cudaGetSymbolAddress((void**)&XcA,   g_XcA);
    cudaGetSymbolAddress((void**)&XcB,   g_XcB);
    cudaGetSymbolAddress((void**)&Abuf,  g_Abuf);
    cudaGetSymbolAddress((void**)&bias2, g_bias2);
    cudaGetSymbolAddress((void**)&part,  g_part);
    cudaGetSymbolAddress((void**)&part2, g_part2);
    cudaGetSymbolAddress((void**)&ppart, g_ppart);
    cudaGetSymbolAddress((void**)&scl,   g_scale);
    cudaGetSymbolAddress((void**)&shf,   g_shift);
    cudaGetSymbolAddress((void**)&attv,  g_att);

    const int GEMM_SMEM = 3 * 32768;
    const int PREP_SMEM = 33024 + 2048 + 2048;
    cudaFuncSetAttribute(gemm_k<0,0,0,0,0>, cudaFuncAttributeMaxDynamicSharedMemorySize, GEMM_SMEM);
    cudaFuncSetAttribute(gemm_k<1,1,1,0,0>, cudaFuncAttributeMaxDynamicSharedMemorySize, GEMM_SMEM);
    cudaFuncSetAttribute(gemm_k<1,0,0,1,0>, cudaFuncAttributeMaxDynamicSharedMemorySize, GEMM_SMEM);
    cudaFuncSetAttribute(gemm_k<0,0,0,0,1>, cudaFuncAttributeMaxDynamicSharedMemorySize, GEMM_SMEM);
    cudaFuncSetAttribute(prep_k<float>,  cudaFuncAttributeMaxDynamicSharedMemorySize, PREP_SMEM);
    cudaFuncSetAttribute(prep_k<__half>, cudaFuncAttributeMaxDynamicSharedMemorySize, PREP_SMEM);

    dim3 ggrid(2, 128, Bb);
    dim3 pgrid(256, Bb);
    dim3 agrid(256, Bb);
    dim3 dgrid(4, Cc, Bb);

    // ---- path 1 ----
    prep_k<float><<<pgrid, 256, PREP_SMEM>>>(x, nullptr, nullptr, XcA, nullptr, part, 0);
    stats2_k<<<Bb, 256>>>(part, gn1_w, gn1_b, scl, shf);
    aprep_k<<<agrid, 256>>>(w1, b1, scl, shf, Abuf, bias2);
    gemm_k<0,0,0,0,0><<<ggrid, 256, GEMM_SMEM>>>(Abuf, XcA, bias2, nullptr, bufAh,
                                                 nullptr, nullptr, nullptr, nullptr,
                                                 nullptr, nullptr);
    dw3x3_k<<<dgrid, 256>>>(bufAh, w2, b2, bufBh);
    prep_k<__half><<<pgrid, 256, PREP_SMEM>>>(bufBh, wg1, bg1, XcB, ppart, nullptr, 1);
    att_k<<<Bb, 256>>>(ppart, w_sca, b_sca, attv);
    aprep_k<<<agrid, 256>>>(w3, b3, attv, nullptr, Abuf, bias2);
    // x1 = y*beta + x(fp16 from XcA) -> XcA (fp16 transposed) + GN2 partials
    gemm_k<1,1,1,0,0><<<ggrid, 256, GEMM_SMEM>>>(Abuf, XcB, bias2, nullptr, nullptr,
                                                 beta, XcA, part2, XcA,
                                                 nullptr, nullptr);

    // ---- path 2 ----
    stats2_k<<<Bb, 256>>>(part2, gn2_w, gn2_b, scl, shf);
    aprep_k<<<agrid, 256>>>(w4, b4, scl, shf, Abuf, bias2);
    // conv4 + gelu^2 + grouped -> XcB directly (no bufAh round-trip)
    gemm_k<0,0,0,0,1><<<ggrid, 256, GEMM_SMEM>>>(Abuf, XcA, bias2, nullptr, nullptr,
                                                 nullptr, nullptr, nullptr, XcB,
                                                 wg2, bg2);
    aprep_k<<<agrid, 256>>>(w5, b5, nullptr, nullptr, Abuf, bias2);
    // out = y*gamma + x1(fp16 from XcA) -> fp32 out
    gemm_k<1,0,0,1,0><<<ggrid, 256, GEMM_SMEM>>>(Abuf, XcB, bias2, out, nullptr,
                                                 gamma, XcA, nullptr, nullptr,
                                                 nullptr, nullptr);
}